// round 10
// baseline (speedup 1.0000x reference)
#include <cuda_runtime.h>
#include <math.h>
#include <stdint.h>

// ---------------- problem constants ----------------
#define Bn 2
#define Ln 1024
#define HIDn 2048
#define NHn 32
#define HDn 64
#define NKVn 8
#define INTERn 8192
#define DSSMn 2048
#define MHn 32
#define MPn 64
#define MSn 64
#define MKn 4
#define CONV_DIMn (DSSMn + 2*MSn)         // 2176
#define QKV_N (NHn*HDn + 2*NKVn*HDn)      // 3072
#define PROJ_N (2*DSSMn + 2*MSn + MHn)    // 4256
#define TOK (Bn*Ln)                       // 2048

#define KEY_MULT 0.7f
#define ATTN_IN 1.2f
#define ATTN_OUT 0.8f
#define SSM_IN 1.1f
#define SSM_OUT 0.9f
#define GATE_MULT 0.9f
#define DOWN_MULT 0.8f
#define EPSf 1e-5f

// ---------------- scratch (device globals; no allocation) ----------------
__device__ float g_hs[TOK*HIDn];
__device__ float g_qkv[TOK*QKV_N];
__device__ float g_attn[TOK*HIDn];
__device__ float g_attn_h[TOK*HIDn];
__device__ float g_proj[(size_t)TOK*PROJ_N];
__device__ float g_conv[(size_t)TOK*CONV_DIMn];
__device__ float g_dt[TOK*MHn];
__device__ float g_y[TOK*DSSMn];
__device__ float g_ssm_h[TOK*HIDn];
__device__ float g_h[TOK*HIDn];
__device__ float g_h2[TOK*HIDn];
__device__ float g_act[(size_t)TOK*INTERn];
// tf32-rounded weight copies
__device__ float g_wqkv[(size_t)QKV_N*HIDn];
__device__ float g_wo[(size_t)HIDn*HIDn];
__device__ float g_win[(size_t)PROJ_N*HIDn];
__device__ float g_wout[(size_t)HIDn*DSSMn];
__device__ float g_wgu[(size_t)2*INTERn*HIDn];   // row-interleaved: 2j=gate*0.9, 2j+1=up
__device__ float g_wdn[(size_t)HIDn*INTERn];

// ---------------- helpers ----------------
__device__ __forceinline__ float tf32r(float x) {
    uint32_t u;
    asm("cvt.rna.tf32.f32 %0, %1;" : "=r"(u) : "f"(x));
    return __uint_as_float(u);
}

__device__ __forceinline__ void mma_tf32(float* c,
                                         uint32_t a0, uint32_t a1, uint32_t a2, uint32_t a3,
                                         uint32_t b0, uint32_t b1) {
    asm volatile(
        "mma.sync.aligned.m16n8k8.row.col.f32.tf32.tf32.f32 "
        "{%0,%1,%2,%3}, {%4,%5,%6,%7}, {%8,%9}, {%0,%1,%2,%3};"
        : "+f"(c[0]), "+f"(c[1]), "+f"(c[2]), "+f"(c[3])
        : "r"(a0), "r"(a1), "r"(a2), "r"(a3), "r"(b0), "r"(b1));
}

__device__ __forceinline__ float block_sum256(float v) {
    __shared__ float sh[8];
    int lane = threadIdx.x & 31;
    int w = threadIdx.x >> 5;
#pragma unroll
    for (int o = 16; o; o >>= 1) v += __shfl_xor_sync(0xffffffffu, v, o);
    if (lane == 0) sh[w] = v;
    __syncthreads();
    if (w == 0) {
        v = (lane < 8) ? sh[lane] : 0.f;
#pragma unroll
        for (int o = 4; o; o >>= 1) v += __shfl_xor_sync(0xffffffffu, v, o);
        if (lane == 0) sh[0] = v;
    }
    __syncthreads();
    return sh[0];
}

// ---------------- weight -> tf32-rounded copy ----------------
__global__ __launch_bounds__(256) void cvtw_k(const float* __restrict__ in,
                                              float* __restrict__ out, int n4) {
    int i = blockIdx.x * blockDim.x + threadIdx.x;
    if (i >= n4) return;
    float4 v = ((const float4*)in)[i];
    v.x = tf32r(v.x); v.y = tf32r(v.y); v.z = tf32r(v.z); v.w = tf32r(v.w);
    ((float4*)out)[i] = v;
}

// gate_up weights: interleave rows (gate j -> 2j, scaled by GATE_MULT; up j -> 2j+1)
__global__ __launch_bounds__(256) void cvtw_gu_k(const float* __restrict__ in,
                                                 float* __restrict__ out) {
    int i = blockIdx.x * blockDim.x + threadIdx.x;
    int n4 = 2*INTERn*(HIDn/4);
    if (i >= n4) return;
    int r = i / (HIDn/4);
    int c4 = i % (HIDn/4);
    float sc = 1.0f;
    int outr;
    if (r < INTERn) { outr = 2*r; sc = GATE_MULT; }
    else            { outr = 2*(r - INTERn) + 1; }
    float4 v = ((const float4*)in)[i];
    v.x = tf32r(v.x*sc); v.y = tf32r(v.y*sc); v.z = tf32r(v.z*sc); v.w = tf32r(v.w*sc);
    ((float4*)out)[(size_t)outr*(HIDn/4) + c4] = v;
}

// ---------------- RMSNorm (output tf32-rounded: feeds GEMM A) ----------------
__global__ __launch_bounds__(256) void rmsnorm_k(const float* __restrict__ x,
                                                 const float* __restrict__ w,
                                                 float* __restrict__ out) {
    int row = blockIdx.x;
    const float4* xr = (const float4*)(x + (size_t)row * HIDn);
    float ss = 0.f;
    for (int i = threadIdx.x; i < HIDn/4; i += 256) {
        float4 v = xr[i];
        ss += v.x*v.x + v.y*v.y + v.z*v.z + v.w*v.w;
    }
    ss = block_sum256(ss);
    float sc = rsqrtf(ss * (1.0f/HIDn) + EPSf);
    float4* orow = (float4*)(out + (size_t)row * HIDn);
    const float4* wr = (const float4*)w;
    for (int i = threadIdx.x; i < HIDn/4; i += 256) {
        float4 v = xr[i]; float4 ww = wr[i];
        v.x = tf32r(v.x*sc*ww.x); v.y = tf32r(v.y*sc*ww.y);
        v.z = tf32r(v.z*sc*ww.z); v.w = tf32r(v.w*sc*ww.w);
        orow[i] = v;
    }
}

// ---------------- TF32 tensor-core GEMM ----------------
// C[M,N] = alpha*A[M,K]@W[N,K]^T (+resid). epi==2: column pairs -> silu(c0)*c1,
// written to C with row stride N/2 (fused SwiGLU activation).
#define GSTR 20

__device__ __forceinline__ void cpa16(uint32_t dst, const float* src, int bytes) {
    asm volatile("cp.async.ca.shared.global [%0], [%1], 16, %2;"
                 :: "r"(dst), "l"(src), "r"(bytes));
}

__global__ __launch_bounds__(256, 2) void tgemm_nt(const float* __restrict__ A,
                                                   const float* __restrict__ W,
                                                   float* __restrict__ C,
                                                   const float* __restrict__ resid,
                                                   int M, int N, int K, float alpha,
                                                   int epi) {
    __shared__ float As[2][128*GSTR];
    __shared__ float Ws[2][128*GSTR];

    int tid = threadIdx.x;
    int bm = blockIdx.y * 128, bn = blockIdx.x * 128;
    int lane = tid & 31, wid = tid >> 5;
    int g = lane >> 2, t = lane & 3;
    int wm = wid & 1, wn_ = wid >> 1;

    int lr = tid >> 1;
    int lk = (tid & 1) * 8;
    const float* Ag = A + (size_t)(bm + lr) * K + lk;
    int wrow = bn + lr;
    const float* Wg = W + (size_t)(wrow < N ? wrow : N-1) * K + lk;
    int wbytes = (wrow < N) ? 16 : 0;
    uint32_t sA = (uint32_t)__cvta_generic_to_shared(&As[0][0]) + (lr*GSTR + lk)*4;
    uint32_t sW = (uint32_t)__cvta_generic_to_shared(&Ws[0][0]) + (lr*GSTR + lk)*4;
    const uint32_t bufB = 128*GSTR*4;

    float acc[4][4][4];
#pragma unroll
    for (int i = 0; i < 4; i++)
#pragma unroll
        for (int j = 0; j < 4; j++)
#pragma unroll
            for (int e = 0; e < 4; e++) acc[i][j][e] = 0.f;

    int nk = K / 16;
    cpa16(sA, Ag, 16); cpa16(sA+16, Ag+4, 16);
    cpa16(sW, Wg, wbytes); cpa16(sW+16, Wg+4, wbytes);
    asm volatile("cp.async.commit_group;");

    for (int kb = 0; kb < nk; kb++) {
        if (kb + 1 < nk) {
            uint32_t o = ((kb+1)&1) * bufB;
            const float* a2 = Ag + (kb+1)*16;
            const float* w2 = Wg + (kb+1)*16;
            cpa16(sA+o, a2, 16); cpa16(sA+o+16, a2+4, 16);
            cpa16(sW+o, w2, wbytes); cpa16(sW+o+16, w2+4, wbytes);
        }
        asm volatile("cp.async.commit_group;");
        asm volatile("cp.async.wait_group 1;");
        __syncthreads();

        const float* ab = &As[kb&1][0] + (wm*64 + g)*GSTR + t;
        const float* bb = &Ws[kb&1][0] + (wn_*32 + g)*GSTR + t;
#pragma unroll
        for (int kk = 0; kk < 16; kk += 8) {
            uint32_t af[4][4], bf[4][2];
#pragma unroll
            for (int mi = 0; mi < 4; mi++) {
                af[mi][0] = __float_as_uint(ab[mi*(16*GSTR) + kk]);
                af[mi][1] = __float_as_uint(ab[mi*(16*GSTR) + 8*GSTR + kk]);
                af[mi][2] = __float_as_uint(ab[mi*(16*GSTR) + kk + 4]);
                af[mi][3] = __float_as_uint(ab[mi*(16*GSTR) + 8*GSTR + kk + 4]);
            }
#pragma unroll
            for (int ni = 0; ni < 4; ni++) {
                bf[ni][0] = __float_as_uint(bb[ni*(8*GSTR) + kk]);
                bf[ni][1] = __float_as_uint(bb[ni*(8*GSTR) + kk + 4]);
            }
#pragma unroll
            for (int mi = 0; mi < 4; mi++)
#pragma unroll
                for (int ni = 0; ni < 4; ni++)
                    mma_tf32(acc[mi][ni], af[mi][0], af[mi][1], af[mi][2], af[mi][3],
                             bf[ni][0], bf[ni][1]);
        }
        __syncthreads();
    }

    if (epi == 2) {
        // fused SwiGLU: cols (cc, cc+1) = (gate, up) -> act[row][cc/2]
        int No = N >> 1;
#pragma unroll
        for (int mi = 0; mi < 4; mi++) {
            int r0 = bm + wm*64 + mi*16 + g;
#pragma unroll
            for (int ni = 0; ni < 4; ni++) {
                int cc = bn + wn_*32 + ni*8 + t*2;
                float gate0 = acc[mi][ni][0], up0 = acc[mi][ni][1];
                float gate1 = acc[mi][ni][2], up1 = acc[mi][ni][3];
                C[(size_t)r0*No + (cc>>1)]     = tf32r(gate0 / (1.f + __expf(-gate0)) * up0);
                C[(size_t)(r0+8)*No + (cc>>1)] = tf32r(gate1 / (1.f + __expf(-gate1)) * up1);
            }
        }
    } else {
#pragma unroll
        for (int mi = 0; mi < 4; mi++) {
            int r0 = bm + wm*64 + mi*16 + g;
            float* c0 = C + (size_t)r0 * N;
            float* c1 = C + (size_t)(r0+8) * N;
            const float* rr0 = resid ? resid + (size_t)r0 * N : nullptr;
            const float* rr1 = resid ? resid + (size_t)(r0+8) * N : nullptr;
#pragma unroll
            for (int ni = 0; ni < 4; ni++) {
                int cc = bn + wn_*32 + ni*8 + t*2;
                if (cc < N) {
                    float2 v0 = make_float2(alpha*acc[mi][ni][0], alpha*acc[mi][ni][1]);
                    float2 v1 = make_float2(alpha*acc[mi][ni][2], alpha*acc[mi][ni][3]);
                    if (rr0) {
                        v0.x += rr0[cc]; v0.y += rr0[cc+1];
                        v1.x += rr1[cc]; v1.y += rr1[cc+1];
                    }
                    *(float2*)(c0 + cc) = v0;
                    *(float2*)(c1 + cc) = v1;
                }
            }
        }
    }
}

// ---------------- RoPE (+ KEY_MULT for K heads), in-place on g_qkv ----------------
__global__ __launch_bounds__(256) void rope_k(const int* __restrict__ positions) {
    const int NHK = NHn + NKVn; // 40
    int idx = blockIdx.x * blockDim.x + threadIdx.x;
    int total = TOK * NHK * (HDn/2);
    if (idx >= total) return;
    int i = idx & 31;
    int head = (idx >> 5) % NHK;
    int row = idx / (32 * NHK);
    int t = row % Ln;
    float pos = (float)positions[t];
    float inv = expf(-(float)(2*i) * (25.328436022934504f / 64.f));
    float ang = pos * inv;
    float sv, cv;
    sincosf(ang, &sv, &cv);
    float mult = 1.f;
    size_t off;
    if (head < NHn) {
        off = (size_t)row * QKV_N + head * HDn;
    } else {
        off = (size_t)row * QKV_N + NHn*HDn + (head - NHn) * HDn;
        mult = KEY_MULT;
    }
    float x1 = g_qkv[off + i];
    float x2 = g_qkv[off + 32 + i];
    g_qkv[off + i]      = (x1 * cv - x2 * sv) * mult;
    g_qkv[off + 32 + i] = (x2 * cv + x1 * sv) * mult;
}

// ---------------- Tensor-core flash attention (tf32, causal, GQA) ----------------
// Block: 128 threads (4 warps), 64 q rows, loop over 64-wide k tiles.
// Warp w owns q rows [w*16, w*16+16). Q fragments live in registers.
// P is written back into Ks (FA2-style); smem stride 68 -> conflict-free B-frag LDS.
#define ASTR 68
__global__ __launch_bounds__(128) void attn_tc_k(const float* __restrict__ qkv,
                                                 float* __restrict__ out) {
    __shared__ float Ks[64][ASTR];
    __shared__ float Vt[64][ASTR];

    int b = blockIdx.y / NHn;
    int h = blockIdx.y % NHn;
    int kvg = h / (NHn / NKVn);
    int q0 = blockIdx.x * 64;
    int tid = threadIdx.x;
    int lane = tid & 31, w = tid >> 5;
    int gi = lane >> 2, t = lane & 3;
    const float* base = qkv + (size_t)(b * Ln) * QKV_N;

    // ---- load Q tile (scaled by 1/8, tf32-rounded) into Ks, build fragments ----
    for (int i = tid; i < 64*16; i += 128) {
        int r = i >> 4, c = (i & 15) * 4;
        float4 v = *(const float4*)(base + (size_t)(q0 + r) * QKV_N + h * HDn + c);
        Ks[r][c]   = tf32r(v.x * 0.125f);
        Ks[r][c+1] = tf32r(v.y * 0.125f);
        Ks[r][c+2] = tf32r(v.z * 0.125f);
        Ks[r][c+3] = tf32r(v.w * 0.125f);
    }
    __syncthreads();
    uint32_t aq[8][4];
#pragma unroll
    for (int kb = 0; kb < 8; kb++) {
        aq[kb][0] = __float_as_uint(Ks[w*16 + gi    ][kb*8 + t]);
        aq[kb][1] = __float_as_uint(Ks[w*16 + gi + 8][kb*8 + t]);
        aq[kb][2] = __float_as_uint(Ks[w*16 + gi    ][kb*8 + t + 4]);
        aq[kb][3] = __float_as_uint(Ks[w*16 + gi + 8][kb*8 + t + 4]);
    }

    float mA = -1e30f, mB = -1e30f, lA = 0.f, lB = 0.f;
    float acco[8][4];
#pragma unroll
    for (int nv = 0; nv < 8; nv++)
#pragma unroll
        for (int e = 0; e < 4; e++) acco[nv][e] = 0.f;

    int nk = blockIdx.x + 1;
    for (int kt = 0; kt < nk; kt++) {
        int k0 = kt * 64;
        __syncthreads();   // prev iter done with Ks(Q or P) / Vt
        // load K tile (rows=seq, cols=hd)
        for (int i = tid; i < 64*16; i += 128) {
            int r = i >> 4, c = (i & 15) * 4;
            float4 v = *(const float4*)(base + (size_t)(k0 + r) * QKV_N + NHn*HDn + kvg * HDn + c);
            Ks[r][c] = tf32r(v.x); Ks[r][c+1] = tf32r(v.y);
            Ks[r][c+2] = tf32r(v.z); Ks[r][c+3] = tf32r(v.w);
        }
        // load V transposed (rows=hd, cols=seq)
        for (int i = tid; i < 64*16; i += 128) {
            int r = i >> 4, c = (i & 15) * 4;
            float4 v = *(const float4*)(base + (size_t)(k0 + r) * QKV_N + NHn*HDn + NKVn*HDn + kvg * HDn + c);
            Vt[c][r] = tf32r(v.x); Vt[c+1][r] = tf32r(v.y);
            Vt[c+2][r] = tf32r(v.z); Vt[c+3][r] = tf32r(v.w);
        }
        __syncthreads();

        // ---- S = Q @ K^T ----
        float accs[8][4];
#pragma unroll
        for (int ns = 0; ns < 8; ns++) {
#pragma unroll
            for (int e = 0; e < 4; e++) accs[ns][e] = 0.f;
#pragma unroll
            for (int kb = 0; kb < 8; kb++) {
                uint32_t b0 = __float_as_uint(Ks[ns*8 + gi][kb*8 + t]);
                uint32_t b1 = __float_as_uint(Ks[ns*8 + gi][kb*8 + t + 4]);
                mma_tf32(accs[ns], aq[kb][0], aq[kb][1], aq[kb][2], aq[kb][3], b0, b1);
            }
        }
        // ---- mask (diagonal tile only) ----
        if (kt == nk - 1) {
            int rA = w*16 + gi, rB = rA + 8;
#pragma unroll
            for (int ns = 0; ns < 8; ns++) {
#pragma unroll
                for (int j = 0; j < 2; j++) {
                    int col = ns*8 + t*2 + j;
                    if (col > rA) accs[ns][j]   = -1e9f;
                    if (col > rB) accs[ns][2+j] = -1e9f;
                }
            }
        }
        // ---- online softmax ----
        float tmA = -1e30f, tmB = -1e30f;
#pragma unroll
        for (int ns = 0; ns < 8; ns++) {
            tmA = fmaxf(tmA, fmaxf(accs[ns][0], accs[ns][1]));
            tmB = fmaxf(tmB, fmaxf(accs[ns][2], accs[ns][3]));
        }
        tmA = fmaxf(tmA, __shfl_xor_sync(0xffffffffu, tmA, 1));
        tmA = fmaxf(tmA, __shfl_xor_sync(0xffffffffu, tmA, 2));
        tmB = fmaxf(tmB, __shfl_xor_sync(0xffffffffu, tmB, 1));
        tmB = fmaxf(tmB, __shfl_xor_sync(0xffffffffu, tmB, 2));
        float mnA = fmaxf(mA, tmA), mnB = fmaxf(mB, tmB);
        float corA = __expf(mA - mnA), corB = __expf(mB - mnB);
        float rsA = 0.f, rsB = 0.f;
#pragma unroll
        for (int ns = 0; ns < 8; ns++) {
            accs[ns][0] = __expf(accs[ns][0] - mnA); rsA += accs[ns][0];
            accs[ns][1] = __expf(accs[ns][1] - mnA); rsA += accs[ns][1];
            accs[ns][2] = __expf(accs[ns][2] - mnB); rsB += accs[ns][2];
            accs[ns][3] = __expf(accs[ns][3] - mnB); rsB += accs[ns][3];
        }
        rsA += __shfl_xor_sync(0xffffffffu, rsA, 1);
        rsA += __shfl_xor_sync(0xffffffffu, rsA, 2);
        rsB += __shfl_xor_sync(0xffffffffu, rsB, 1);
        rsB += __shfl_xor_sync(0xffffffffu, rsB, 2);
        lA = lA * corA + rsA; lB = lB * corB + rsB;
        mA = mnA; mB = mnB;
#pragma unroll
        for (int nv = 0; nv < 8; nv++) {
            acco[nv][0] *= corA; acco[nv][1] *= corA;
            acco[nv][2] *= corB; acco[nv][3] *= corB;
        }
        __syncthreads();   // all warps done reading Ks as K
        // ---- write P into Ks (rows = q local, cols = seq local) ----
#pragma unroll
        for (int ns = 0; ns < 8; ns++) {
            Ks[w*16 + gi    ][ns*8 + t*2]     = tf32r(accs[ns][0]);
            Ks[w*16 + gi    ][ns*8 + t*2 + 1] = tf32r(accs[ns][1]);
            Ks[w*16 + gi + 8][ns*8 + t*2]     = tf32r(accs[ns][2]);
            Ks[w*16 + gi + 8][ns*8 + t*2 + 1] = tf32r(accs[ns][3]);
        }
        __syncthreads();
        // ---- O += P @ V ----
#pragma unroll
        for (int kb = 0; kb < 8; kb++) {
            uint32_t a0 = __float_as_uint(Ks[w*16 + gi    ][kb*8 + t]);
            uint32_t a1 = __float_as_uint(Ks[w*16 + gi + 8][kb*8 + t]);
            uint32_t a2 = __float_as_uint(Ks[w*16 + gi    ][kb*8 + t + 4]);
            uint32_t a3 = __float_as_uint(Ks[w*16 + gi + 8][kb*8 + t + 4]);
#pragma unroll
            for (int nv = 0; nv < 8; nv++) {
                uint32_t b0 = __float_as_uint(Vt[nv*8 + gi][kb*8 + t]);
                uint32_t b1 = __float_as_uint(Vt[nv*8 + gi][kb*8 + t + 4]);
                mma_tf32(acco[nv], a0, a1, a2, a3, b0, b1);
            }
        }
    }

    float invA = 1.f / lA, invB = 1.f / lB;
    int rowA = b*Ln + q0 + w*16 + gi;
#pragma unroll
    for (int nv = 0; nv < 8; nv++) {
        int cc = h*HDn + nv*8 + t*2;
        float2 vA = make_float2(tf32r(acco[nv][0]*invA), tf32r(acco[nv][1]*invA));
        float2 vB = make_float2(tf32r(acco[nv][2]*invB), tf32r(acco[nv][3]*invB));
        *(float2*)(out + (size_t)rowA * HIDn + cc)     = vA;
        *(float2*)(out + (size_t)(rowA+8) * HIDn + cc) = vB;
    }
}

// ---------------- causal conv1d (+mup, +bias, +silu) over xBC ----------------
__global__ __launch_bounds__(256) void conv_k(const float* __restrict__ conv_w,
                                              const float* __restrict__ conv_b) {
    int idx = blockIdx.x * blockDim.x + threadIdx.x;
    if (idx >= Bn*Ln*CONV_DIMn) return;
    int c = idx % CONV_DIMn;
    int t = (idx / CONV_DIMn) % Ln;
    int b = idx / (CONV_DIMn * Ln);
    float mup = (c < DSSMn) ? 0.9f : ((c < DSSMn + MSn) ? 0.8f : 1.1f);
    float4 w = *(const float4*)(conv_w + c*4);
    float wk[4] = {w.x, w.y, w.z, w.w};
    float s = 0.f;
#pragma unroll
    for (int k = 0; k < MKn; k++) {
        int tt = t - (MKn-1) + k;
        if (tt >= 0)
            s += g_proj[(size_t)(b*Ln + tt) * PROJ_N + DSSMn + c] * wk[k];
    }
    float acc = conv_b[c] + mup * s;
    g_conv[idx] = acc / (1.f + __expf(-acc));
}

// ---------------- dt = softplus(proj_dt * 1.2 + dt_bias) ----------------
__global__ __launch_bounds__(256) void dt_k(const float* __restrict__ dt_bias) {
    int idx = blockIdx.x * blockDim.x + threadIdx.x;
    if (idx >= TOK*MHn) return;
    int h = idx % MHn;
    float v = g_proj[(size_t)(idx / MHn) * PROJ_N + (2*DSSMn + 2*MSn) + h] * 1.2f + dt_bias[h];
    g_dt[idx] = (v > 20.f) ? v : log1pf(__expf(v));
}

// ---------------- selective scan (Mamba2), one block per (b,h), prefetched ----------------
__global__ __launch_bounds__(512) void scan_k(const float* __restrict__ A_log,
                                              const float* __restrict__ Dv) {
    int b = blockIdx.x >> 5;
    int h = blockIdx.x & 31;
    int tid = threadIdx.x;
    int p = tid >> 3;
    int s0 = (tid & 7) << 3;
    float Ah = -expf(A_log[h]);
    float Dh = Dv[h];
    float st[8] = {0,0,0,0,0,0,0,0};

    // prefetch t=0
    size_t base = (size_t)(b*Ln) * CONV_DIMn;
    float dt_c = g_dt[(b*Ln) * MHn + h];
    float xv_c = g_conv[base + h*MPn + p];
    float4 bv0_c = *(const float4*)(g_conv + base + DSSMn + s0);
    float4 bv1_c = *(const float4*)(g_conv + base + DSSMn + s0 + 4);
    float4 cv0_c = *(const float4*)(g_conv + base + DSSMn + MSn + s0);
    float4 cv1_c = *(const float4*)(g_conv + base + DSSMn + MSn + s0 + 4);

    for (int t = 0; t < Ln; t++) {
        float dt_n = 0.f, xv_n = 0.f;
        float4 bv0_n, bv1_n, cv0_n, cv1_n;
        if (t + 1 < Ln) {
            size_t nb = (size_t)(b*Ln + t + 1) * CONV_DIMn;
            dt_n = g_dt[(b*Ln + t + 1) * MHn + h];
            xv_n = g_conv[nb + h*MPn + p];
            bv0_n = *(const float4*)(g_conv + nb + DSSMn + s0);
            bv1_n = *(const float4*)(g_conv + nb + DSSMn + s0 + 4);
            cv0_n = *(const float4*)(g_conv + nb + DSSMn + MSn + s0);
            cv1_n = *(const float4*)(g_conv + nb + DSSMn + MSn + s0 + 4);
        } else {
            bv0_n = bv1_n = cv0_n = cv1_n = make_float4(0.f,0.f,0.f,0.f);
        }

        float dA = __expf(dt_c * Ah);
        float coef = dt_c * xv_c;
        float y = 0.f;
        st[0] = st[0]*dA + coef*bv0_c.x; y += st[0]*cv0_c.x;
        st[1] = st[1]*dA + coef*bv0_c.y; y += st[1]*cv0_c.y;
        st[2] = st[2]*dA + coef*bv0_c.z; y += st[2]*cv0_c.z;
        st[3] = st[3]*dA + coef*bv0_c.w; y += st[3]*cv0_c.w;
        st[4] = st[4]*dA + coef*bv1_c.x; y += st[4]*cv1_c.x;
        st[5] = st[5]*dA + coef*bv1_c.y; y += st[5]*cv1_c.y;
        st[6] = st[6]*dA + coef*bv1_c.z; y += st[6]*cv1_c.z;
        st[7] = st[7]*dA + coef*bv1_c.w; y += st[7]*cv1_c.w;
        y += __shfl_xor_sync(0xffffffffu, y, 1);
        y += __shfl_xor_sync(0xffffffffu, y, 2);
        y += __shfl_xor_sync(0xffffffffu, y, 4);
        if ((tid & 7) == 0)
            g_y[(size_t)(b*Ln + t) * DSSMn + h*MPn + p] = y + xv_c * Dh;

        dt_c = dt_n; xv_c = xv_n;
        bv0_c = bv0_n; bv1_c = bv1_n; cv0_c = cv0_n; cv1_c = cv1_n;
    }
}

// ---------------- gate (y * silu(z)) + RMSNorm; output tf32-rounded ----------------
__global__ __launch_bounds__(256) void gate_rms_k(const float* __restrict__ nw) {
    int row = blockIdx.x;
    const float* zp = g_proj + (size_t)row * PROJ_N;
    float* yp = g_y + (size_t)row * DSSMn;
    float ss = 0.f;
    for (int i = threadIdx.x; i < DSSMn; i += 256) {
        float z = zp[i];
        float gval = yp[i] * (z / (1.f + __expf(-z)));
        yp[i] = gval;
        ss += gval * gval;
    }
    ss = block_sum256(ss);
    float sc = rsqrtf(ss * (1.f/DSSMn) + EPSf);
    for (int i = threadIdx.x; i < DSSMn; i += 256)
        yp[i] = tf32r(yp[i] * sc * nw[i]);
}

// ---------------- fused: h = attn+ssm+resid (store g_h) ; h2 = rms(h) (store g_h2) ----------------
__global__ __launch_bounds__(256) void combine_rms_k(const float* __restrict__ hidden,
                                                     const float* __restrict__ w) {
    __shared__ float hrow[HIDn];
    int row = blockIdx.x;
    const float4* ap = (const float4*)(g_attn_h + (size_t)row * HIDn);
    const float4* sp = (const float4*)(g_ssm_h + (size_t)row * HIDn);
    const float4* rp = (const float4*)(hidden + (size_t)row * HIDn);
    float4* hp = (float4*)(g_h + (size_t)row * HIDn);
    float ss = 0.f;
    for (int i = threadIdx.x; i < HIDn/4; i += 256) {
        float4 a = ap[i], s = sp[i], r = rp[i];
        float4 o;
        o.x = a.x + s.x + r.x; o.y = a.y + s.y + r.y;
        o.z = a.z + s.z + r.z; o.w = a.w + s.w + r.w;
        hp[i] = o;
        ((float4*)hrow)[i] = o;
        ss += o.x*o.x + o.y*o.y + o.z*o.z + o.w*o.w;
    }
    ss = block_sum256(ss);
    float sc = rsqrtf(ss * (1.0f/HIDn) + EPSf);
    float4* o2 = (float4*)(g_h2 + (size_t)row * HIDn);
    const float4* wr = (const float4*)w;
    for (int i = threadIdx.x; i < HIDn/4; i += 256) {
        float4 v = ((float4*)hrow)[i]; float4 ww = wr[i];
        v.x = tf32r(v.x*sc*ww.x); v.y = tf32r(v.y*sc*ww.y);
        v.z = tf32r(v.z*sc*ww.z); v.w = tf32r(v.w*sc*ww.w);
        o2[i] = v;
    }
}

// ---------------- host launcher ----------------
static float* sym(const void* s) {
    void* p = nullptr;
    cudaGetSymbolAddress(&p, s);
    return (float*)p;
}

extern "C" void kernel_launch(void* const* d_in, const int* in_sizes, int n_in,
                              void* d_out, int out_size) {
    const float* hidden     = (const float*)d_in[0];
    const int*   positions  = (const int*)  d_in[1];
    const float* w_in_ln    = (const float*)d_in[2];
    const float* qkv_w      = (const float*)d_in[3];
    const float* o_w        = (const float*)d_in[4];
    const float* in_proj_w  = (const float*)d_in[5];
    const float* conv_w     = (const float*)d_in[6];
    const float* conv_b     = (const float*)d_in[7];
    const float* A_log      = (const float*)d_in[8];
    const float* dt_bias    = (const float*)d_in[9];
    const float* Dv         = (const float*)d_in[10];
    const float* ssm_norm_w = (const float*)d_in[11];
    const float* out_proj_w = (const float*)d_in[12];
    const float* w_pre_ff   = (const float*)d_in[13];
    const float* gate_up_w  = (const float*)d_in[14];
    const float* down_w     = (const float*)d_in[15];
    float* out = (float*)d_out;

    float* p_hs     = sym(g_hs);
    float* p_qkv    = sym(g_qkv);
    float* p_attn   = sym(g_attn);
    float* p_attn_h = sym(g_attn_h);
    float* p_proj   = sym(g_proj);
    float* p_y      = sym(g_y);
    float* p_ssm_h  = sym(g_ssm_h);
    float* p_h      = sym(g_h);
    float* p_h2     = sym(g_h2);
    float* p_act    = sym(g_act);
    float* p_wqkv   = sym(g_wqkv);
    float* p_wo     = sym(g_wo);
    float* p_win    = sym(g_win);
    float* p_wout   = sym(g_wout);
    float* p_wgu    = sym(g_wgu);
    float* p_wdn    = sym(g_wdn);

    // 0. tf32-round the weights (gate_up also row-interleaved + GATE_MULT folded)
    {
        struct { const float* in; float* out; size_t n; } W[5] = {
            {qkv_w,     p_wqkv, (size_t)QKV_N*HIDn},
            {o_w,       p_wo,   (size_t)HIDn*HIDn},
            {in_proj_w, p_win,  (size_t)PROJ_N*HIDn},
            {out_proj_w,p_wout, (size_t)HIDn*DSSMn},
            {down_w,    p_wdn,  (size_t)HIDn*INTERn},
        };
        for (int i = 0; i < 5; i++) {
            int n4 = (int)(W[i].n / 4);
            cvtw_k<<<(n4 + 255)/256, 256>>>(W[i].in, W[i].out, n4);
        }
        int n4gu = 2*INTERn*(HIDn/4);
        cvtw_gu_k<<<(n4gu + 255)/256, 256>>>(gate_up_w, p_wgu);
    }

    // 1. input RMSNorm (tf32-rounded output)
    rmsnorm_k<<<TOK, 256>>>(hidden, w_in_ln, p_hs);

    // 2. qkv projection (fold ATTN_IN)
    tgemm_nt<<<dim3(QKV_N/128, TOK/128), 256>>>(p_hs, p_wqkv, p_qkv, nullptr,
                                                TOK, QKV_N, HIDn, ATTN_IN, 0);
    // 3. RoPE + key mult
    {
        int total = TOK * (NHn + NKVn) * (HDn/2);
        rope_k<<<(total + 255)/256, 256>>>(positions);
    }
    // 4. attention (tensor cores)
    attn_tc_k<<<dim3(Ln/64, Bn*NHn), 128>>>(p_qkv, p_attn);
    // 5. o projection (fold ATTN_OUT)
    tgemm_nt<<<dim3(HIDn/128, TOK/128), 256>>>(p_attn, p_wo, p_attn_h, nullptr,
                                               TOK, HIDn, HIDn, ATTN_OUT, 0);

    // 6. SSM in_proj (fold SSM_IN)
    tgemm_nt<<<dim3((PROJ_N + 127)/128, TOK/128), 256>>>(p_hs, p_win, p_proj, nullptr,
                                                         TOK, PROJ_N, HIDn, SSM_IN, 0);
    // 7. conv + silu ; dt softplus
    conv_k<<<(Bn*Ln*CONV_DIMn + 255)/256, 256>>>(conv_w, conv_b);
    dt_k<<<(TOK*MHn + 255)/256, 256>>>(dt_bias);
    // 8. selective scan
    scan_k<<<Bn*MHn, 512>>>(A_log, Dv);
    // 9. gate + RMS (tf32-rounded output)
    gate_rms_k<<<TOK, 256>>>(ssm_norm_w);
    // 10. out_proj (fold SSM_OUT)
    tgemm_nt<<<dim3(HIDn/128, TOK/128), 256>>>(p_y, p_wout, p_ssm_h, nullptr,
                                               TOK, HIDn, DSSMn, SSM_OUT, 0);

    // 11. residual combine + pre-FF RMSNorm (fused)
    combine_rms_k<<<TOK, 256>>>(hidden, w_pre_ff);

    // 12. MLP: gate_up with fused SwiGLU epilogue -> g_act, then down (+resid)
    tgemm_nt<<<dim3((2*INTERn)/128, TOK/128), 256>>>(p_h2, p_wgu, p_act, nullptr,
                                                     TOK, 2*INTERn, HIDn, 1.0f, 2);
    tgemm_nt<<<dim3(HIDn/128, TOK/128), 256>>>(p_act, p_wdn, out, p_h,
                                               TOK, HIDn, INTERn, DOWN_MULT, 0);
}

// round 11
// speedup vs baseline: 1.4365x; 1.4365x over previous
#include <cuda_runtime.h>
#include <math.h>
#include <stdint.h>

// ---------------- problem constants ----------------
#define Bn 2
#define Ln 1024
#define HIDn 2048
#define NHn 32
#define HDn 64
#define NKVn 8
#define INTERn 8192
#define DSSMn 2048
#define MHn 32
#define MPn 64
#define MSn 64
#define MKn 4
#define CONV_DIMn (DSSMn + 2*MSn)         // 2176
#define QKV_N (NHn*HDn + 2*NKVn*HDn)      // 3072
#define PROJ_N (2*DSSMn + 2*MSn + MHn)    // 4256
#define TOK (Bn*Ln)                       // 2048

#define KEY_MULT 0.7f
#define ATTN_IN 1.2f
#define ATTN_OUT 0.8f
#define SSM_IN 1.1f
#define SSM_OUT 0.9f
#define GATE_MULT 0.9f
#define DOWN_MULT 0.8f
#define EPSf 1e-5f

// ---------------- scratch (device globals; no allocation) ----------------
__device__ float g_hs[TOK*HIDn];
__device__ float g_qkv[TOK*QKV_N];
__device__ float g_attn[TOK*HIDn];
__device__ float g_attn_h[TOK*HIDn];
__device__ float g_proj[(size_t)TOK*PROJ_N];
__device__ float g_conv[(size_t)TOK*CONV_DIMn];
__device__ float g_dt[TOK*MHn];
__device__ float g_y[TOK*DSSMn];
__device__ float g_ssm_h[TOK*HIDn];
__device__ float g_h[TOK*HIDn];
__device__ float g_h2[TOK*HIDn];
__device__ float g_act[(size_t)TOK*INTERn];
// tf32-rounded weight copies
__device__ float g_wqkv[(size_t)QKV_N*HIDn];
__device__ float g_wo[(size_t)HIDn*HIDn];
__device__ float g_win[(size_t)PROJ_N*HIDn];
__device__ float g_wout[(size_t)HIDn*DSSMn];
__device__ float g_wgu[(size_t)2*INTERn*HIDn];   // row-interleaved: 2j=gate*0.9, 2j+1=up
__device__ float g_wdn[(size_t)HIDn*INTERn];

// ---------------- helpers ----------------
__device__ __forceinline__ float tf32r(float x) {
    uint32_t u;
    asm("cvt.rna.tf32.f32 %0, %1;" : "=r"(u) : "f"(x));
    return __uint_as_float(u);
}

__device__ __forceinline__ void mma_tf32(float* c,
                                         uint32_t a0, uint32_t a1, uint32_t a2, uint32_t a3,
                                         uint32_t b0, uint32_t b1) {
    asm volatile(
        "mma.sync.aligned.m16n8k8.row.col.f32.tf32.tf32.f32 "
        "{%0,%1,%2,%3}, {%4,%5,%6,%7}, {%8,%9}, {%0,%1,%2,%3};"
        : "+f"(c[0]), "+f"(c[1]), "+f"(c[2]), "+f"(c[3])
        : "r"(a0), "r"(a1), "r"(a2), "r"(a3), "r"(b0), "r"(b1));
}

__device__ __forceinline__ float block_sum256(float v) {
    __shared__ float sh[8];
    int lane = threadIdx.x & 31;
    int w = threadIdx.x >> 5;
#pragma unroll
    for (int o = 16; o; o >>= 1) v += __shfl_xor_sync(0xffffffffu, v, o);
    if (lane == 0) sh[w] = v;
    __syncthreads();
    if (w == 0) {
        v = (lane < 8) ? sh[lane] : 0.f;
#pragma unroll
        for (int o = 4; o; o >>= 1) v += __shfl_xor_sync(0xffffffffu, v, o);
        if (lane == 0) sh[0] = v;
    }
    __syncthreads();
    return sh[0];
}

// ---------------- weight -> tf32-rounded copy ----------------
__global__ __launch_bounds__(256) void cvtw_k(const float* __restrict__ in,
                                              float* __restrict__ out, int n4) {
    int i = blockIdx.x * blockDim.x + threadIdx.x;
    if (i >= n4) return;
    float4 v = ((const float4*)in)[i];
    v.x = tf32r(v.x); v.y = tf32r(v.y); v.z = tf32r(v.z); v.w = tf32r(v.w);
    ((float4*)out)[i] = v;
}

// gate_up weights: interleave rows (gate j -> 2j, scaled by GATE_MULT; up j -> 2j+1)
__global__ __launch_bounds__(256) void cvtw_gu_k(const float* __restrict__ in,
                                                 float* __restrict__ out) {
    int i = blockIdx.x * blockDim.x + threadIdx.x;
    int n4 = 2*INTERn*(HIDn/4);
    if (i >= n4) return;
    int r = i / (HIDn/4);
    int c4 = i % (HIDn/4);
    float sc = 1.0f;
    int outr;
    if (r < INTERn) { outr = 2*r; sc = GATE_MULT; }
    else            { outr = 2*(r - INTERn) + 1; }
    float4 v = ((const float4*)in)[i];
    v.x = tf32r(v.x*sc); v.y = tf32r(v.y*sc); v.z = tf32r(v.z*sc); v.w = tf32r(v.w*sc);
    ((float4*)out)[(size_t)outr*(HIDn/4) + c4] = v;
}

// ---------------- RMSNorm (output tf32-rounded: feeds GEMM A) ----------------
__global__ __launch_bounds__(256) void rmsnorm_k(const float* __restrict__ x,
                                                 const float* __restrict__ w,
                                                 float* __restrict__ out) {
    int row = blockIdx.x;
    const float4* xr = (const float4*)(x + (size_t)row * HIDn);
    float ss = 0.f;
    for (int i = threadIdx.x; i < HIDn/4; i += 256) {
        float4 v = xr[i];
        ss += v.x*v.x + v.y*v.y + v.z*v.z + v.w*v.w;
    }
    ss = block_sum256(ss);
    float sc = rsqrtf(ss * (1.0f/HIDn) + EPSf);
    float4* orow = (float4*)(out + (size_t)row * HIDn);
    const float4* wr = (const float4*)w;
    for (int i = threadIdx.x; i < HIDn/4; i += 256) {
        float4 v = xr[i]; float4 ww = wr[i];
        v.x = tf32r(v.x*sc*ww.x); v.y = tf32r(v.y*sc*ww.y);
        v.z = tf32r(v.z*sc*ww.z); v.w = tf32r(v.w*sc*ww.w);
        orow[i] = v;
    }
}

// ---------------- TF32 tensor-core GEMM (plain epilogue; byte-identical hot loop to R9) ----------------
#define GSTR 20

__device__ __forceinline__ void cpa16(uint32_t dst, const float* src, int bytes) {
    asm volatile("cp.async.ca.shared.global [%0], [%1], 16, %2;"
                 :: "r"(dst), "l"(src), "r"(bytes));
}

// shared mainloop body as a macro so the two GEMM kernels compile independently
#define TGEMM_MAINLOOP(ACC)                                                          \
    int tid = threadIdx.x;                                                           \
    int bm = blockIdx.y * 128, bn = blockIdx.x * 128;                                \
    int lane = tid & 31, wid = tid >> 5;                                             \
    int g = lane >> 2, t = lane & 3;                                                 \
    int wm = wid & 1, wn_ = wid >> 1;                                                \
    int lr = tid >> 1;                                                               \
    int lk = (tid & 1) * 8;                                                          \
    const float* Ag = A + (size_t)(bm + lr) * K + lk;                                \
    int wrow = bn + lr;                                                              \
    const float* Wg = W + (size_t)(wrow < N ? wrow : N-1) * K + lk;                  \
    int wbytes = (wrow < N) ? 16 : 0;                                                \
    uint32_t sA = (uint32_t)__cvta_generic_to_shared(&As[0][0]) + (lr*GSTR + lk)*4;  \
    uint32_t sW = (uint32_t)__cvta_generic_to_shared(&Ws[0][0]) + (lr*GSTR + lk)*4;  \
    const uint32_t bufB = 128*GSTR*4;                                                \
    _Pragma("unroll")                                                                \
    for (int i = 0; i < 4; i++)                                                      \
        _Pragma("unroll")                                                            \
        for (int j = 0; j < 4; j++)                                                  \
            _Pragma("unroll")                                                        \
            for (int e = 0; e < 4; e++) ACC[i][j][e] = 0.f;                          \
    int nk = K / 16;                                                                 \
    cpa16(sA, Ag, 16); cpa16(sA+16, Ag+4, 16);                                       \
    cpa16(sW, Wg, wbytes); cpa16(sW+16, Wg+4, wbytes);                               \
    asm volatile("cp.async.commit_group;");                                          \
    for (int kb = 0; kb < nk; kb++) {                                                \
        if (kb + 1 < nk) {                                                           \
            uint32_t o = ((kb+1)&1) * bufB;                                          \
            const float* a2 = Ag + (kb+1)*16;                                        \
            const float* w2 = Wg + (kb+1)*16;                                        \
            cpa16(sA+o, a2, 16); cpa16(sA+o+16, a2+4, 16);                           \
            cpa16(sW+o, w2, wbytes); cpa16(sW+o+16, w2+4, wbytes);                   \
        }                                                                            \
        asm volatile("cp.async.commit_group;");                                      \
        asm volatile("cp.async.wait_group 1;");                                      \
        __syncthreads();                                                             \
        const float* ab = &As[kb&1][0] + (wm*64 + g)*GSTR + t;                       \
        const float* bb = &Ws[kb&1][0] + (wn_*32 + g)*GSTR + t;                      \
        _Pragma("unroll")                                                            \
        for (int kk = 0; kk < 16; kk += 8) {                                         \
            uint32_t af[4][4], bf[4][2];                                             \
            _Pragma("unroll")                                                        \
            for (int mi = 0; mi < 4; mi++) {                                         \
                af[mi][0] = __float_as_uint(ab[mi*(16*GSTR) + kk]);                  \
                af[mi][1] = __float_as_uint(ab[mi*(16*GSTR) + 8*GSTR + kk]);         \
                af[mi][2] = __float_as_uint(ab[mi*(16*GSTR) + kk + 4]);              \
                af[mi][3] = __float_as_uint(ab[mi*(16*GSTR) + 8*GSTR + kk + 4]);     \
            }                                                                        \
            _Pragma("unroll")                                                        \
            for (int ni = 0; ni < 4; ni++) {                                         \
                bf[ni][0] = __float_as_uint(bb[ni*(8*GSTR) + kk]);                   \
                bf[ni][1] = __float_as_uint(bb[ni*(8*GSTR) + kk + 4]);               \
            }                                                                        \
            _Pragma("unroll")                                                        \
            for (int mi = 0; mi < 4; mi++)                                           \
                _Pragma("unroll")                                                    \
                for (int ni = 0; ni < 4; ni++)                                       \
                    mma_tf32(ACC[mi][ni], af[mi][0], af[mi][1], af[mi][2], af[mi][3],\
                             bf[ni][0], bf[ni][1]);                                  \
        }                                                                            \
        __syncthreads();                                                             \
    }

__global__ __launch_bounds__(256, 2) void tgemm_nt(const float* __restrict__ A,
                                                   const float* __restrict__ W,
                                                   float* __restrict__ C,
                                                   const float* __restrict__ resid,
                                                   int M, int N, int K, float alpha) {
    __shared__ float As[2][128*GSTR];
    __shared__ float Ws[2][128*GSTR];
    float acc[4][4][4];
    TGEMM_MAINLOOP(acc)
#pragma unroll
    for (int mi = 0; mi < 4; mi++) {
        int r0 = bm + wm*64 + mi*16 + g;
        float* c0 = C + (size_t)r0 * N;
        float* c1 = C + (size_t)(r0+8) * N;
        const float* rr0 = resid ? resid + (size_t)r0 * N : nullptr;
        const float* rr1 = resid ? resid + (size_t)(r0+8) * N : nullptr;
#pragma unroll
        for (int ni = 0; ni < 4; ni++) {
            int cc = bn + wn_*32 + ni*8 + t*2;
            if (cc < N) {
                float2 v0 = make_float2(alpha*acc[mi][ni][0], alpha*acc[mi][ni][1]);
                float2 v1 = make_float2(alpha*acc[mi][ni][2], alpha*acc[mi][ni][3]);
                if (rr0) {
                    v0.x += rr0[cc]; v0.y += rr0[cc+1];
                    v1.x += rr1[cc]; v1.y += rr1[cc+1];
                }
                *(float2*)(c0 + cc) = v0;
                *(float2*)(c1 + cc) = v1;
            }
        }
    }
}

// clone with fused SwiGLU epilogue (gate/up row-interleaved weights):
// cols (2j, 2j+1) = (gate*0.9, up) -> C[row][ (bn+...)/2 ] = tf32r(silu(gate)*up)
__global__ __launch_bounds__(256, 2) void tgemm_gu(const float* __restrict__ A,
                                                   const float* __restrict__ W,
                                                   float* __restrict__ C,
                                                   int M, int N, int K) {
    __shared__ float As[2][128*GSTR];
    __shared__ float Ws[2][128*GSTR];
    float acc[4][4][4];
    TGEMM_MAINLOOP(acc)
    int No = N >> 1;
#pragma unroll
    for (int mi = 0; mi < 4; mi++) {
        int r0 = bm + wm*64 + mi*16 + g;
#pragma unroll
        for (int ni = 0; ni < 4; ni++) {
            int cc = bn + wn_*32 + ni*8 + t*2;
            float gate0 = acc[mi][ni][0], up0 = acc[mi][ni][1];
            float gate1 = acc[mi][ni][2], up1 = acc[mi][ni][3];
            C[(size_t)r0*No + (cc>>1)]     = tf32r(gate0 / (1.f + __expf(-gate0)) * up0);
            C[(size_t)(r0+8)*No + (cc>>1)] = tf32r(gate1 / (1.f + __expf(-gate1)) * up1);
        }
    }
}

// ---------------- RoPE (+ KEY_MULT for K heads), in-place on g_qkv ----------------
__global__ __launch_bounds__(256) void rope_k(const int* __restrict__ positions) {
    const int NHK = NHn + NKVn; // 40
    int idx = blockIdx.x * blockDim.x + threadIdx.x;
    int total = TOK * NHK * (HDn/2);
    if (idx >= total) return;
    int i = idx & 31;
    int head = (idx >> 5) % NHK;
    int row = idx / (32 * NHK);
    int t = row % Ln;
    float pos = (float)positions[t];
    float inv = expf(-(float)(2*i) * (25.328436022934504f / 64.f));
    float ang = pos * inv;
    float sv, cv;
    sincosf(ang, &sv, &cv);
    float mult = 1.f;
    size_t off;
    if (head < NHn) {
        off = (size_t)row * QKV_N + head * HDn;
    } else {
        off = (size_t)row * QKV_N + NHn*HDn + (head - NHn) * HDn;
        mult = KEY_MULT;
    }
    float x1 = g_qkv[off + i];
    float x2 = g_qkv[off + 32 + i];
    g_qkv[off + i]      = (x1 * cv - x2 * sv) * mult;
    g_qkv[off + 32 + i] = (x2 * cv + x1 * sv) * mult;
}

// ---------------- Flash attention (fp32, causal, GQA); out tf32-rounded (R9 version) ----------------
__global__ __launch_bounds__(256) void attn_k(const float* __restrict__ qkv,
                                              float* __restrict__ out) {
    const int TQ = 32, TK = 64;
    __shared__ float Qs[TQ][HDn + 1];
    __shared__ float KPs[TK][HDn + 1];
    __shared__ float Vs[TK][HDn];

    int b = blockIdx.y / NHn;
    int h = blockIdx.y % NHn;
    int g = h / (NHn / NKVn);
    int q0 = blockIdx.x * TQ;
    int tid = threadIdx.x, tx = tid & 15, ty = tid >> 4;
    const float* base = qkv + (size_t)(b * Ln) * QKV_N;

    for (int i = tid; i < TQ * (HDn/4); i += 256) {
        int r = i >> 4, c = (i & 15) * 4;
        float4 v = *(const float4*)(base + (size_t)(q0 + r) * QKV_N + h * HDn + c);
        Qs[r][c] = v.x; Qs[r][c+1] = v.y; Qs[r][c+2] = v.z; Qs[r][c+3] = v.w;
    }

    float m0 = -1e30f, m1 = -1e30f, l0 = 0.f, l1 = 0.f;
    float o0[4] = {0,0,0,0}, o1[4] = {0,0,0,0};
    int ktiles = (q0 + TQ - 1) / TK + 1;

    for (int kt = 0; kt < ktiles; kt++) {
        int k0 = kt * TK;
        __syncthreads();
        for (int i = tid; i < TK * (HDn/4); i += 256) {
            int r = i >> 4, c = (i & 15) * 4;
            float4 v = *(const float4*)(base + (size_t)(k0 + r) * QKV_N + NHn*HDn + g * HDn + c);
            KPs[r][c] = v.x; KPs[r][c+1] = v.y; KPs[r][c+2] = v.z; KPs[r][c+3] = v.w;
        }
        __syncthreads();

        float s0[4] = {0,0,0,0}, s1[4] = {0,0,0,0};
#pragma unroll 8
        for (int kk = 0; kk < HDn; kk++) {
            float q0v = Qs[ty*2][kk], q1v = Qs[ty*2+1][kk];
#pragma unroll
            for (int j = 0; j < 4; j++) {
                float kv = KPs[tx*4+j][kk];
                s0[j] += q0v * kv;
                s1[j] += q1v * kv;
            }
        }
        const float sc = 0.125f;
        bool needmask = (k0 + TK - 1 > q0);
        int qg0 = q0 + ty*2, qg1 = qg0 + 1;
#pragma unroll
        for (int j = 0; j < 4; j++) {
            s0[j] *= sc; s1[j] *= sc;
            if (needmask) {
                int kg = k0 + tx*4 + j;
                if (kg > qg0) s0[j] = -1e9f;
                if (kg > qg1) s1[j] = -1e9f;
            }
        }
        float tm0 = fmaxf(fmaxf(s0[0], s0[1]), fmaxf(s0[2], s0[3]));
        float tm1 = fmaxf(fmaxf(s1[0], s1[1]), fmaxf(s1[2], s1[3]));
#pragma unroll
        for (int o = 8; o; o >>= 1) {
            tm0 = fmaxf(tm0, __shfl_xor_sync(0xffffffffu, tm0, o));
            tm1 = fmaxf(tm1, __shfl_xor_sync(0xffffffffu, tm1, o));
        }
        float mn0 = fmaxf(m0, tm0), mn1 = fmaxf(m1, tm1);
        float cor0 = __expf(m0 - mn0), cor1 = __expf(m1 - mn1);
        float rs0 = 0.f, rs1 = 0.f;
#pragma unroll
        for (int j = 0; j < 4; j++) {
            s0[j] = __expf(s0[j] - mn0); rs0 += s0[j];
            s1[j] = __expf(s1[j] - mn1); rs1 += s1[j];
        }
#pragma unroll
        for (int o = 8; o; o >>= 1) {
            rs0 += __shfl_xor_sync(0xffffffffu, rs0, o);
            rs1 += __shfl_xor_sync(0xffffffffu, rs1, o);
        }
        l0 = l0 * cor0 + rs0; l1 = l1 * cor1 + rs1;
        m0 = mn0; m1 = mn1;
#pragma unroll
        for (int j = 0; j < 4; j++) { o0[j] *= cor0; o1[j] *= cor1; }

        __syncthreads();
#pragma unroll
        for (int j = 0; j < 4; j++) {
            KPs[ty*2  ][tx*4+j] = s0[j];
            KPs[ty*2+1][tx*4+j] = s1[j];
        }
        for (int i = tid; i < TK * (HDn/4); i += 256) {
            int r = i >> 4, c = (i & 15) * 4;
            float4 v = *(const float4*)(base + (size_t)(k0 + r) * QKV_N + NHn*HDn + NKVn*HDn + g * HDn + c);
            Vs[r][c] = v.x; Vs[r][c+1] = v.y; Vs[r][c+2] = v.z; Vs[r][c+3] = v.w;
        }
        __syncthreads();
#pragma unroll 8
        for (int kk = 0; kk < TK; kk++) {
            float p0 = KPs[ty*2][kk], p1 = KPs[ty*2+1][kk];
#pragma unroll
            for (int j = 0; j < 4; j++) {
                float vv = Vs[kk][tx*4+j];
                o0[j] += p0 * vv;
                o1[j] += p1 * vv;
            }
        }
    }
    float inv0 = 1.f / l0, inv1 = 1.f / l1;
    float4 r0 = make_float4(tf32r(o0[0]*inv0), tf32r(o0[1]*inv0), tf32r(o0[2]*inv0), tf32r(o0[3]*inv0));
    float4 r1 = make_float4(tf32r(o1[0]*inv1), tf32r(o1[1]*inv1), tf32r(o1[2]*inv1), tf32r(o1[3]*inv1));
    *(float4*)(out + (size_t)(b*Ln + q0 + ty*2    ) * HIDn + h*HDn + tx*4) = r0;
    *(float4*)(out + (size_t)(b*Ln + q0 + ty*2 + 1) * HIDn + h*HDn + tx*4) = r1;
}

// ---------------- causal conv1d (+mup, +bias, +silu) over xBC ----------------
__global__ __launch_bounds__(256) void conv_k(const float* __restrict__ conv_w,
                                              const float* __restrict__ conv_b) {
    int idx = blockIdx.x * blockDim.x + threadIdx.x;
    if (idx >= Bn*Ln*CONV_DIMn) return;
    int c = idx % CONV_DIMn;
    int t = (idx / CONV_DIMn) % Ln;
    int b = idx / (CONV_DIMn * Ln);
    float mup = (c < DSSMn) ? 0.9f : ((c < DSSMn + MSn) ? 0.8f : 1.1f);
    float4 w = *(const float4*)(conv_w + c*4);
    float wk[4] = {w.x, w.y, w.z, w.w};
    float s = 0.f;
#pragma unroll
    for (int k = 0; k < MKn; k++) {
        int tt = t - (MKn-1) + k;
        if (tt >= 0)
            s += g_proj[(size_t)(b*Ln + tt) * PROJ_N + DSSMn + c] * wk[k];
    }
    float acc = conv_b[c] + mup * s;
    g_conv[idx] = acc / (1.f + __expf(-acc));
}

// ---------------- dt = softplus(proj_dt * 1.2 + dt_bias) ----------------
__global__ __launch_bounds__(256) void dt_k(const float* __restrict__ dt_bias) {
    int idx = blockIdx.x * blockDim.x + threadIdx.x;
    if (idx >= TOK*MHn) return;
    int h = idx % MHn;
    float v = g_proj[(size_t)(idx / MHn) * PROJ_N + (2*DSSMn + 2*MSn) + h] * 1.2f + dt_bias[h];
    g_dt[idx] = (v > 20.f) ? v : log1pf(__expf(v));
}

// ---------------- selective scan (Mamba2), one block per (b,h), prefetched ----------------
__global__ __launch_bounds__(512) void scan_k(const float* __restrict__ A_log,
                                              const float* __restrict__ Dv) {
    int b = blockIdx.x >> 5;
    int h = blockIdx.x & 31;
    int tid = threadIdx.x;
    int p = tid >> 3;
    int s0 = (tid & 7) << 3;
    float Ah = -expf(A_log[h]);
    float Dh = Dv[h];
    float st[8] = {0,0,0,0,0,0,0,0};

    size_t base = (size_t)(b*Ln) * CONV_DIMn;
    float dt_c = g_dt[(b*Ln) * MHn + h];
    float xv_c = g_conv[base + h*MPn + p];
    float4 bv0_c = *(const float4*)(g_conv + base + DSSMn + s0);
    float4 bv1_c = *(const float4*)(g_conv + base + DSSMn + s0 + 4);
    float4 cv0_c = *(const float4*)(g_conv + base + DSSMn + MSn + s0);
    float4 cv1_c = *(const float4*)(g_conv + base + DSSMn + MSn + s0 + 4);

    for (int t = 0; t < Ln; t++) {
        float dt_n = 0.f, xv_n = 0.f;
        float4 bv0_n, bv1_n, cv0_n, cv1_n;
        if (t + 1 < Ln) {
            size_t nb = (size_t)(b*Ln + t + 1) * CONV_DIMn;
            dt_n = g_dt[(b*Ln + t + 1) * MHn + h];
            xv_n = g_conv[nb + h*MPn + p];
            bv0_n = *(const float4*)(g_conv + nb + DSSMn + s0);
            bv1_n = *(const float4*)(g_conv + nb + DSSMn + s0 + 4);
            cv0_n = *(const float4*)(g_conv + nb + DSSMn + MSn + s0);
            cv1_n = *(const float4*)(g_conv + nb + DSSMn + MSn + s0 + 4);
        } else {
            bv0_n = bv1_n = cv0_n = cv1_n = make_float4(0.f,0.f,0.f,0.f);
        }

        float dA = __expf(dt_c * Ah);
        float coef = dt_c * xv_c;
        float y = 0.f;
        st[0] = st[0]*dA + coef*bv0_c.x; y += st[0]*cv0_c.x;
        st[1] = st[1]*dA + coef*bv0_c.y; y += st[1]*cv0_c.y;
        st[2] = st[2]*dA + coef*bv0_c.z; y += st[2]*cv0_c.z;
        st[3] = st[3]*dA + coef*bv0_c.w; y += st[3]*cv0_c.w;
        st[4] = st[4]*dA + coef*bv1_c.x; y += st[4]*cv1_c.x;
        st[5] = st[5]*dA + coef*bv1_c.y; y += st[5]*cv1_c.y;
        st[6] = st[6]*dA + coef*bv1_c.z; y += st[6]*cv1_c.z;
        st[7] = st[7]*dA + coef*bv1_c.w; y += st[7]*cv1_c.w;
        y += __shfl_xor_sync(0xffffffffu, y, 1);
        y += __shfl_xor_sync(0xffffffffu, y, 2);
        y += __shfl_xor_sync(0xffffffffu, y, 4);
        if ((tid & 7) == 0)
            g_y[(size_t)(b*Ln + t) * DSSMn + h*MPn + p] = y + xv_c * Dh;

        dt_c = dt_n; xv_c = xv_n;
        bv0_c = bv0_n; bv1_c = bv1_n; cv0_c = cv0_n; cv1_c = cv1_n;
    }
}

// ---------------- gate (y * silu(z)) + RMSNorm; output tf32-rounded ----------------
__global__ __launch_bounds__(256) void gate_rms_k(const float* __restrict__ nw) {
    int row = blockIdx.x;
    const float* zp = g_proj + (size_t)row * PROJ_N;
    float* yp = g_y + (size_t)row * DSSMn;
    float ss = 0.f;
    for (int i = threadIdx.x; i < DSSMn; i += 256) {
        float z = zp[i];
        float gval = yp[i] * (z / (1.f + __expf(-z)));
        yp[i] = gval;
        ss += gval * gval;
    }
    ss = block_sum256(ss);
    float sc = rsqrtf(ss * (1.f/DSSMn) + EPSf);
    for (int i = threadIdx.x; i < DSSMn; i += 256)
        yp[i] = tf32r(yp[i] * sc * nw[i]);
}

// ---------------- fused: h = attn+ssm+resid (store g_h) ; h2 = rms(h)*w (store g_h2) ----------------
__global__ __launch_bounds__(256) void combine_rms_k(const float* __restrict__ hidden,
                                                     const float* __restrict__ w) {
    __shared__ float hrow[HIDn];
    int row = blockIdx.x;
    const float4* ap = (const float4*)(g_attn_h + (size_t)row * HIDn);
    const float4* sp = (const float4*)(g_ssm_h + (size_t)row * HIDn);
    const float4* rp = (const float4*)(hidden + (size_t)row * HIDn);
    float4* hp = (float4*)(g_h + (size_t)row * HIDn);
    float ss = 0.f;
    for (int i = threadIdx.x; i < HIDn/4; i += 256) {
        float4 a = ap[i], s = sp[i], r = rp[i];
        float4 o;
        o.x = a.x + s.x + r.x; o.y = a.y + s.y + r.y;
        o.z = a.z + s.z + r.z; o.w = a.w + s.w + r.w;
        hp[i] = o;
        ((float4*)hrow)[i] = o;
        ss += o.x*o.x + o.y*o.y + o.z*o.z + o.w*o.w;
    }
    ss = block_sum256(ss);
    float sc = rsqrtf(ss * (1.0f/HIDn) + EPSf);
    float4* o2 = (float4*)(g_h2 + (size_t)row * HIDn);
    const float4* wr = (const float4*)w;
    for (int i = threadIdx.x; i < HIDn/4; i += 256) {
        float4 v = ((float4*)hrow)[i]; float4 ww = wr[i];
        v.x = tf32r(v.x*sc*ww.x); v.y = tf32r(v.y*sc*ww.y);
        v.z = tf32r(v.z*sc*ww.z); v.w = tf32r(v.w*sc*ww.w);
        o2[i] = v;
    }
}

// ---------------- host launcher ----------------
static float* sym(const void* s) {
    void* p = nullptr;
    cudaGetSymbolAddress(&p, s);
    return (float*)p;
}

extern "C" void kernel_launch(void* const* d_in, const int* in_sizes, int n_in,
                              void* d_out, int out_size) {
    const float* hidden     = (const float*)d_in[0];
    const int*   positions  = (const int*)  d_in[1];
    const float* w_in_ln    = (const float*)d_in[2];
    const float* qkv_w      = (const float*)d_in[3];
    const float* o_w        = (const float*)d_in[4];
    const float* in_proj_w  = (const float*)d_in[5];
    const float* conv_w     = (const float*)d_in[6];
    const float* conv_b     = (const float*)d_in[7];
    const float* A_log      = (const float*)d_in[8];
    const float* dt_bias    = (const float*)d_in[9];
    const float* Dv         = (const float*)d_in[10];
    const float* ssm_norm_w = (const float*)d_in[11];
    const float* out_proj_w = (const float*)d_in[12];
    const float* w_pre_ff   = (const float*)d_in[13];
    const float* gate_up_w  = (const float*)d_in[14];
    const float* down_w     = (const float*)d_in[15];
    float* out = (float*)d_out;

    float* p_hs     = sym(g_hs);
    float* p_qkv    = sym(g_qkv);
    float* p_attn   = sym(g_attn);
    float* p_attn_h = sym(g_attn_h);
    float* p_proj   = sym(g_proj);
    float* p_y      = sym(g_y);
    float* p_ssm_h  = sym(g_ssm_h);
    float* p_h      = sym(g_h);
    float* p_h2     = sym(g_h2);
    float* p_act    = sym(g_act);
    float* p_wqkv   = sym(g_wqkv);
    float* p_wo     = sym(g_wo);
    float* p_win    = sym(g_win);
    float* p_wout   = sym(g_wout);
    float* p_wgu    = sym(g_wgu);
    float* p_wdn    = sym(g_wdn);

    // 0. tf32-round the weights (gate_up also row-interleaved + GATE_MULT folded)
    {
        struct { const float* in; float* out; size_t n; } W[5] = {
            {qkv_w,     p_wqkv, (size_t)QKV_N*HIDn},
            {o_w,       p_wo,   (size_t)HIDn*HIDn},
            {in_proj_w, p_win,  (size_t)PROJ_N*HIDn},
            {out_proj_w,p_wout, (size_t)HIDn*DSSMn},
            {down_w,    p_wdn,  (size_t)HIDn*INTERn},
        };
        for (int i = 0; i < 5; i++) {
            int n4 = (int)(W[i].n / 4);
            cvtw_k<<<(n4 + 255)/256, 256>>>(W[i].in, W[i].out, n4);
        }
        int n4gu = 2*INTERn*(HIDn/4);
        cvtw_gu_k<<<(n4gu + 255)/256, 256>>>(gate_up_w, p_wgu);
    }

    // 1. input RMSNorm (tf32-rounded output)
    rmsnorm_k<<<TOK, 256>>>(hidden, w_in_ln, p_hs);

    // 2. qkv projection (fold ATTN_IN)
    tgemm_nt<<<dim3(QKV_N/128, TOK/128), 256>>>(p_hs, p_wqkv, p_qkv, nullptr,
                                                TOK, QKV_N, HIDn, ATTN_IN);
    // 3. RoPE + key mult
    {
        int total = TOK * (NHn + NKVn) * (HDn/2);
        rope_k<<<(total + 255)/256, 256>>>(positions);
    }
    // 4. attention (scalar flash, known 492us)
    attn_k<<<dim3(Ln/32, Bn*NHn), 256>>>(p_qkv, p_attn);
    // 5. o projection (fold ATTN_OUT)
    tgemm_nt<<<dim3(HIDn/128, TOK/128), 256>>>(p_attn, p_wo, p_attn_h, nullptr,
                                               TOK, HIDn, HIDn, ATTN_OUT);

    // 6. SSM in_proj (fold SSM_IN)
    tgemm_nt<<<dim3((PROJ_N + 127)/128, TOK/128), 256>>>(p_hs, p_win, p_proj, nullptr,
                                                         TOK, PROJ_N, HIDn, SSM_IN);
    // 7. conv + silu ; dt softplus
    conv_k<<<(Bn*Ln*CONV_DIMn + 255)/256, 256>>>(conv_w, conv_b);
    dt_k<<<(TOK*MHn + 255)/256, 256>>>(dt_bias);
    // 8. selective scan (prefetched)
    scan_k<<<Bn*MHn, 512>>>(A_log, Dv);
    // 9. gate + RMS (tf32-rounded output)
    gate_rms_k<<<TOK, 256>>>(ssm_norm_w);
    // 10. out_proj (fold SSM_OUT)
    tgemm_nt<<<dim3(HIDn/128, TOK/128), 256>>>(p_y, p_wout, p_ssm_h, nullptr,
                                               TOK, HIDn, DSSMn, SSM_OUT);

    // 11. residual combine + pre-FF RMSNorm (fused)
    combine_rms_k<<<TOK, 256>>>(hidden, w_pre_ff);

    // 12. MLP: gate_up with fused SwiGLU epilogue (separate kernel) -> g_act, then down (+resid)
    tgemm_gu<<<dim3((2*INTERn)/128, TOK/128), 256>>>(p_h2, p_wgu, p_act,
                                                     TOK, 2*INTERn, HIDn);
    tgemm_nt<<<dim3(HIDn/128, TOK/128), 256>>>(p_act, p_wdn, out, p_h,
                                               TOK, HIDn, INTERn, DOWN_MULT);
}

// round 12
// speedup vs baseline: 2.1325x; 1.4846x over previous
#include <cuda_runtime.h>
#include <cuda_fp16.h>
#include <math.h>
#include <stdint.h>

// ---------------- problem constants ----------------
#define Bn 2
#define Ln 1024
#define HIDn 2048
#define NHn 32
#define HDn 64
#define NKVn 8
#define INTERn 8192
#define DSSMn 2048
#define MHn 32
#define MPn 64
#define MSn 64
#define MKn 4
#define CONV_DIMn (DSSMn + 2*MSn)         // 2176
#define QKV_N (NHn*HDn + 2*NKVn*HDn)      // 3072
#define PROJ_N (2*DSSMn + 2*MSn + MHn)    // 4256
#define TOK (Bn*Ln)                       // 2048

#define KEY_MULT 0.7f
#define ATTN_IN 1.2f
#define ATTN_OUT 0.8f
#define SSM_IN 1.1f
#define SSM_OUT 0.9f
#define GATE_MULT 0.9f
#define DOWN_MULT 0.8f
#define EPSf 1e-5f

// ---------------- scratch (device globals; no allocation) ----------------
__device__ __half g_hs[TOK*HIDn];                    // rms output (GEMM A)
__device__ float  g_qkv[TOK*QKV_N];
__device__ __half g_attn[TOK*HIDn];                  // attn output (GEMM A)
__device__ float  g_attn_h[TOK*HIDn];
__device__ float  g_proj[(size_t)TOK*PROJ_N];
__device__ float  g_conv[(size_t)TOK*CONV_DIMn];
__device__ float  g_dt[TOK*MHn];
__device__ float  g_y[TOK*DSSMn];                    // scan output (fp32)
__device__ __half g_yh[TOK*DSSMn];                   // gated+rms'd (GEMM A)
__device__ float  g_ssm_h[TOK*HIDn];
__device__ float  g_h[TOK*HIDn];                     // residual (fp32)
__device__ __half g_h2h[TOK*HIDn];                   // pre-FF rms (GEMM A)
__device__ __half g_act[(size_t)TOK*INTERn];         // swiglu output (GEMM A)
// fp16 weight copies
__device__ __half g_wqkv[(size_t)QKV_N*HIDn];
__device__ __half g_wo[(size_t)HIDn*HIDn];
__device__ __half g_win[(size_t)PROJ_N*HIDn];
__device__ __half g_wout[(size_t)HIDn*DSSMn];
__device__ __half g_wgu[(size_t)2*INTERn*HIDn];      // row-interleaved: 2j=gate*0.9, 2j+1=up
__device__ __half g_wdn[(size_t)HIDn*INTERn];

// ---------------- helpers ----------------
__device__ __forceinline__ void mma_f16(float* c,
                                        uint32_t a0, uint32_t a1, uint32_t a2, uint32_t a3,
                                        uint32_t b0, uint32_t b1) {
    asm volatile(
        "mma.sync.aligned.m16n8k16.row.col.f32.f16.f16.f32 "
        "{%0,%1,%2,%3}, {%4,%5,%6,%7}, {%8,%9}, {%0,%1,%2,%3};"
        : "+f"(c[0]), "+f"(c[1]), "+f"(c[2]), "+f"(c[3])
        : "r"(a0), "r"(a1), "r"(a2), "r"(a3), "r"(b0), "r"(b1));
}

__device__ __forceinline__ float block_sum256(float v) {
    __shared__ float sh[8];
    int lane = threadIdx.x & 31;
    int w = threadIdx.x >> 5;
#pragma unroll
    for (int o = 16; o; o >>= 1) v += __shfl_xor_sync(0xffffffffu, v, o);
    if (lane == 0) sh[w] = v;
    __syncthreads();
    if (w == 0) {
        v = (lane < 8) ? sh[lane] : 0.f;
#pragma unroll
        for (int o = 4; o; o >>= 1) v += __shfl_xor_sync(0xffffffffu, v, o);
        if (lane == 0) sh[0] = v;
    }
    __syncthreads();
    return sh[0];
}

// ---------------- weight -> fp16 copy ----------------
__global__ __launch_bounds__(256) void cvtw_k(const float* __restrict__ in,
                                              __half* __restrict__ out, int n4) {
    int i = blockIdx.x * blockDim.x + threadIdx.x;
    if (i >= n4) return;
    float4 v = ((const float4*)in)[i];
    __half2 h01 = __floats2half2_rn(v.x, v.y);
    __half2 h23 = __floats2half2_rn(v.z, v.w);
    ((__half2*)out)[i*2]   = h01;
    ((__half2*)out)[i*2+1] = h23;
}

// gate_up weights: interleave rows (gate j -> 2j, scaled by GATE_MULT; up j -> 2j+1)
__global__ __launch_bounds__(256) void cvtw_gu_k(const float* __restrict__ in,
                                                 __half* __restrict__ out) {
    int i = blockIdx.x * blockDim.x + threadIdx.x;
    int n4 = 2*INTERn*(HIDn/4);
    if (i >= n4) return;
    int r = i / (HIDn/4);
    int c4 = i % (HIDn/4);
    float sc = 1.0f;
    int outr;
    if (r < INTERn) { outr = 2*r; sc = GATE_MULT; }
    else            { outr = 2*(r - INTERn) + 1; }
    float4 v = ((const float4*)in)[i];
    __half2 h01 = __floats2half2_rn(v.x*sc, v.y*sc);
    __half2 h23 = __floats2half2_rn(v.z*sc, v.w*sc);
    size_t o2 = ((size_t)outr*(HIDn/4) + c4)*2;
    ((__half2*)out)[o2]   = h01;
    ((__half2*)out)[o2+1] = h23;
}

// ---------------- RMSNorm (fp16 output: feeds GEMM A) ----------------
__global__ __launch_bounds__(256) void rmsnorm_k(const float* __restrict__ x,
                                                 const float* __restrict__ w,
                                                 __half* __restrict__ out) {
    int row = blockIdx.x;
    const float4* xr = (const float4*)(x + (size_t)row * HIDn);
    float ss = 0.f;
    for (int i = threadIdx.x; i < HIDn/4; i += 256) {
        float4 v = xr[i];
        ss += v.x*v.x + v.y*v.y + v.z*v.z + v.w*v.w;
    }
    ss = block_sum256(ss);
    float sc = rsqrtf(ss * (1.0f/HIDn) + EPSf);
    __half2* orow = (__half2*)(out + (size_t)row * HIDn);
    const float4* wr = (const float4*)w;
    for (int i = threadIdx.x; i < HIDn/4; i += 256) {
        float4 v = xr[i]; float4 ww = wr[i];
        orow[i*2]   = __floats2half2_rn(v.x*sc*ww.x, v.y*sc*ww.y);
        orow[i*2+1] = __floats2half2_rn(v.z*sc*ww.z, v.w*sc*ww.w);
    }
}

// ---------------- FP16 tensor-core GEMM ----------------
// C[M,N] = alpha*A[M,K]@W[N,K]^T (+resid). A,W fp16; accum fp32.
// 128x128x32 tile, 256 threads, 8 warps (2x4), warp tile 64x32, mma m16n8k16.
#define HSTR 40   // halves per smem row (32 + 8 pad) -> conflict-free frag LDS

__device__ __forceinline__ void cpa16(uint32_t dst, const void* src, int bytes) {
    asm volatile("cp.async.ca.shared.global [%0], [%1], 16, %2;"
                 :: "r"(dst), "l"(src), "r"(bytes));
}

#define TGEMM16_MAINLOOP(ACC)                                                        \
    int tid = threadIdx.x;                                                           \
    int bm = blockIdx.y * 128, bn = blockIdx.x * 128;                                \
    int lane = tid & 31, wid = tid >> 5;                                             \
    int g = lane >> 2, t = lane & 3;                                                 \
    int wm = wid & 1, wn_ = wid >> 1;                                                \
    int lr = tid >> 1;                                                               \
    int lc = (tid & 1) * 2;  /* 16B-chunk base; each thread: chunks lc, lc+1 */      \
    const __half* Ag = A + (size_t)(bm + lr) * K + lc*8;                             \
    int wrow = bn + lr;                                                              \
    const __half* Wg = W + (size_t)(wrow < N ? wrow : N-1) * K + lc*8;               \
    int wbytes = (wrow < N) ? 16 : 0;                                                \
    uint32_t sA = (uint32_t)__cvta_generic_to_shared(&As[0][0]) + (lr*HSTR + lc*8)*2;\
    uint32_t sW = (uint32_t)__cvta_generic_to_shared(&Ws[0][0]) + (lr*HSTR + lc*8)*2;\
    const uint32_t bufB = 128*HSTR*2;                                                \
    _Pragma("unroll")                                                                \
    for (int i = 0; i < 4; i++)                                                      \
        _Pragma("unroll")                                                            \
        for (int j = 0; j < 4; j++)                                                  \
            _Pragma("unroll")                                                        \
            for (int e = 0; e < 4; e++) ACC[i][j][e] = 0.f;                          \
    int nk = K / 32;                                                                 \
    cpa16(sA, Ag, 16); cpa16(sA+16, Ag+8, 16);                                       \
    cpa16(sW, Wg, wbytes); cpa16(sW+16, Wg+8, wbytes);                               \
    asm volatile("cp.async.commit_group;");                                          \
    for (int kb = 0; kb < nk; kb++) {                                                \
        if (kb + 1 < nk) {                                                           \
            uint32_t o = ((kb+1)&1) * bufB;                                          \
            const __half* a2 = Ag + (kb+1)*32;                                       \
            const __half* w2 = Wg + (kb+1)*32;                                       \
            cpa16(sA+o, a2, 16); cpa16(sA+o+16, a2+8, 16);                           \
            cpa16(sW+o, w2, wbytes); cpa16(sW+o+16, w2+8, wbytes);                   \
        }                                                                            \
        asm volatile("cp.async.commit_group;");                                      \
        asm volatile("cp.async.wait_group 1;");                                      \
        __syncthreads();                                                             \
        const uint32_t* Ab = (const uint32_t*)&As[kb&1][0];                          \
        const uint32_t* Bb = (const uint32_t*)&Ws[kb&1][0];                          \
        _Pragma("unroll")                                                            \
        for (int ks = 0; ks < 2; ks++) {                                             \
            uint32_t af[4][4], bf[4][2];                                             \
            _Pragma("unroll")                                                        \
            for (int mi = 0; mi < 4; mi++) {                                         \
                int base = (wm*64 + mi*16 + g)*(HSTR/2) + ks*8 + t;                  \
                af[mi][0] = Ab[base];                                                \
                af[mi][1] = Ab[base + 8*(HSTR/2)];                                   \
                af[mi][2] = Ab[base + 4];                                            \
                af[mi][3] = Ab[base + 8*(HSTR/2) + 4];                               \
            }                                                                        \
            _Pragma("unroll")                                                        \
            for (int ni = 0; ni < 4; ni++) {                                         \
                int nb = (wn_*32 + ni*8 + g)*(HSTR/2) + ks*8 + t;                    \
                bf[ni][0] = Bb[nb];                                                  \
                bf[ni][1] = Bb[nb + 4];                                              \
            }                                                                        \
            _Pragma("unroll")                                                        \
            for (int mi = 0; mi < 4; mi++)                                           \
                _Pragma("unroll")                                                    \
                for (int ni = 0; ni < 4; ni++)                                       \
                    mma_f16(ACC[mi][ni], af[mi][0], af[mi][1], af[mi][2], af[mi][3], \
                            bf[ni][0], bf[ni][1]);                                   \
        }                                                                            \
        __syncthreads();                                                             \
    }

__global__ __launch_bounds__(256, 2) void tgemm_nt(const __half* __restrict__ A,
                                                   const __half* __restrict__ W,
                                                   float* __restrict__ C,
                                                   const float* __restrict__ resid,
                                                   int M, int N, int K, float alpha) {
    __shared__ __half As[2][128*HSTR];
    __shared__ __half Ws[2][128*HSTR];
    float acc[4][4][4];
    TGEMM16_MAINLOOP(acc)
#pragma unroll
    for (int mi = 0; mi < 4; mi++) {
        int r0 = bm + wm*64 + mi*16 + g;
        float* c0 = C + (size_t)r0 * N;
        float* c1 = C + (size_t)(r0+8) * N;
        const float* rr0 = resid ? resid + (size_t)r0 * N : nullptr;
        const float* rr1 = resid ? resid + (size_t)(r0+8) * N : nullptr;
#pragma unroll
        for (int ni = 0; ni < 4; ni++) {
            int cc = bn + wn_*32 + ni*8 + t*2;
            if (cc < N) {
                float2 v0 = make_float2(alpha*acc[mi][ni][0], alpha*acc[mi][ni][1]);
                float2 v1 = make_float2(alpha*acc[mi][ni][2], alpha*acc[mi][ni][3]);
                if (rr0) {
                    v0.x += rr0[cc]; v0.y += rr0[cc+1];
                    v1.x += rr1[cc]; v1.y += rr1[cc+1];
                }
                *(float2*)(c0 + cc) = v0;
                *(float2*)(c1 + cc) = v1;
            }
        }
    }
}

// clone with fused SwiGLU epilogue (gate/up row-interleaved weights):
// cols (2j, 2j+1) = (gate*0.9, up) -> C[row][cc/2] = fp16(silu(gate)*up)
__global__ __launch_bounds__(256, 2) void tgemm_gu(const __half* __restrict__ A,
                                                   const __half* __restrict__ W,
                                                   __half* __restrict__ C,
                                                   int M, int N, int K) {
    __shared__ __half As[2][128*HSTR];
    __shared__ __half Ws[2][128*HSTR];
    float acc[4][4][4];
    TGEMM16_MAINLOOP(acc)
    int No = N >> 1;
#pragma unroll
    for (int mi = 0; mi < 4; mi++) {
        int r0 = bm + wm*64 + mi*16 + g;
#pragma unroll
        for (int ni = 0; ni < 4; ni++) {
            int cc = bn + wn_*32 + ni*8 + t*2;
            float gate0 = acc[mi][ni][0], up0 = acc[mi][ni][1];
            float gate1 = acc[mi][ni][2], up1 = acc[mi][ni][3];
            C[(size_t)r0*No + (cc>>1)]     = __float2half_rn(gate0 / (1.f + __expf(-gate0)) * up0);
            C[(size_t)(r0+8)*No + (cc>>1)] = __float2half_rn(gate1 / (1.f + __expf(-gate1)) * up1);
        }
    }
}

// ---------------- RoPE (+ KEY_MULT for K heads), in-place on g_qkv ----------------
__global__ __launch_bounds__(256) void rope_k(const int* __restrict__ positions) {
    const int NHK = NHn + NKVn; // 40
    int idx = blockIdx.x * blockDim.x + threadIdx.x;
    int total = TOK * NHK * (HDn/2);
    if (idx >= total) return;
    int i = idx & 31;
    int head = (idx >> 5) % NHK;
    int row = idx / (32 * NHK);
    int t = row % Ln;
    float pos = (float)positions[t];
    float inv = expf(-(float)(2*i) * (25.328436022934504f / 64.f));
    float ang = pos * inv;
    float sv, cv;
    sincosf(ang, &sv, &cv);
    float mult = 1.f;
    size_t off;
    if (head < NHn) {
        off = (size_t)row * QKV_N + head * HDn;
    } else {
        off = (size_t)row * QKV_N + NHn*HDn + (head - NHn) * HDn;
        mult = KEY_MULT;
    }
    float x1 = g_qkv[off + i];
    float x2 = g_qkv[off + 32 + i];
    g_qkv[off + i]      = (x1 * cv - x2 * sv) * mult;
    g_qkv[off + 32 + i] = (x2 * cv + x1 * sv) * mult;
}

// ---------------- Flash attention (fp32, causal, GQA); fp16 output ----------------
__global__ __launch_bounds__(256) void attn_k(const float* __restrict__ qkv,
                                              __half* __restrict__ out) {
    const int TQ = 32, TK = 64;
    __shared__ float Qs[TQ][HDn + 1];
    __shared__ float KPs[TK][HDn + 1];
    __shared__ float Vs[TK][HDn];

    int b = blockIdx.y / NHn;
    int h = blockIdx.y % NHn;
    int g = h / (NHn / NKVn);
    int q0 = blockIdx.x * TQ;
    int tid = threadIdx.x, tx = tid & 15, ty = tid >> 4;
    const float* base = qkv + (size_t)(b * Ln) * QKV_N;

    for (int i = tid; i < TQ * (HDn/4); i += 256) {
        int r = i >> 4, c = (i & 15) * 4;
        float4 v = *(const float4*)(base + (size_t)(q0 + r) * QKV_N + h * HDn + c);
        Qs[r][c] = v.x; Qs[r][c+1] = v.y; Qs[r][c+2] = v.z; Qs[r][c+3] = v.w;
    }

    float m0 = -1e30f, m1 = -1e30f, l0 = 0.f, l1 = 0.f;
    float o0[4] = {0,0,0,0}, o1[4] = {0,0,0,0};
    int ktiles = (q0 + TQ - 1) / TK + 1;

    for (int kt = 0; kt < ktiles; kt++) {
        int k0 = kt * TK;
        __syncthreads();
        for (int i = tid; i < TK * (HDn/4); i += 256) {
            int r = i >> 4, c = (i & 15) * 4;
            float4 v = *(const float4*)(base + (size_t)(k0 + r) * QKV_N + NHn*HDn + g * HDn + c);
            KPs[r][c] = v.x; KPs[r][c+1] = v.y; KPs[r][c+2] = v.z; KPs[r][c+3] = v.w;
        }
        __syncthreads();

        float s0[4] = {0,0,0,0}, s1[4] = {0,0,0,0};
#pragma unroll 8
        for (int kk = 0; kk < HDn; kk++) {
            float q0v = Qs[ty*2][kk], q1v = Qs[ty*2+1][kk];
#pragma unroll
            for (int j = 0; j < 4; j++) {
                float kv = KPs[tx*4+j][kk];
                s0[j] += q0v * kv;
                s1[j] += q1v * kv;
            }
        }
        const float sc = 0.125f;
        bool needmask = (k0 + TK - 1 > q0);
        int qg0 = q0 + ty*2, qg1 = qg0 + 1;
#pragma unroll
        for (int j = 0; j < 4; j++) {
            s0[j] *= sc; s1[j] *= sc;
            if (needmask) {
                int kg = k0 + tx*4 + j;
                if (kg > qg0) s0[j] = -1e9f;
                if (kg > qg1) s1[j] = -1e9f;
            }
        }
        float tm0 = fmaxf(fmaxf(s0[0], s0[1]), fmaxf(s0[2], s0[3]));
        float tm1 = fmaxf(fmaxf(s1[0], s1[1]), fmaxf(s1[2], s1[3]));
#pragma unroll
        for (int o = 8; o; o >>= 1) {
            tm0 = fmaxf(tm0, __shfl_xor_sync(0xffffffffu, tm0, o));
            tm1 = fmaxf(tm1, __shfl_xor_sync(0xffffffffu, tm1, o));
        }
        float mn0 = fmaxf(m0, tm0), mn1 = fmaxf(m1, tm1);
        float cor0 = __expf(m0 - mn0), cor1 = __expf(m1 - mn1);
        float rs0 = 0.f, rs1 = 0.f;
#pragma unroll
        for (int j = 0; j < 4; j++) {
            s0[j] = __expf(s0[j] - mn0); rs0 += s0[j];
            s1[j] = __expf(s1[j] - mn1); rs1 += s1[j];
        }
#pragma unroll
        for (int o = 8; o; o >>= 1) {
            rs0 += __shfl_xor_sync(0xffffffffu, rs0, o);
            rs1 += __shfl_xor_sync(0xffffffffu, rs1, o);
        }
        l0 = l0 * cor0 + rs0; l1 = l1 * cor1 + rs1;
        m0 = mn0; m1 = mn1;
#pragma unroll
        for (int j = 0; j < 4; j++) { o0[j] *= cor0; o1[j] *= cor1; }

        __syncthreads();
#pragma unroll
        for (int j = 0; j < 4; j++) {
            KPs[ty*2  ][tx*4+j] = s0[j];
            KPs[ty*2+1][tx*4+j] = s1[j];
        }
        for (int i = tid; i < TK * (HDn/4); i += 256) {
            int r = i >> 4, c = (i & 15) * 4;
            float4 v = *(const float4*)(base + (size_t)(k0 + r) * QKV_N + NHn*HDn + NKVn*HDn + g * HDn + c);
            Vs[r][c] = v.x; Vs[r][c+1] = v.y; Vs[r][c+2] = v.z; Vs[r][c+3] = v.w;
        }
        __syncthreads();
#pragma unroll 8
        for (int kk = 0; kk < TK; kk++) {
            float p0 = KPs[ty*2][kk], p1 = KPs[ty*2+1][kk];
#pragma unroll
            for (int j = 0; j < 4; j++) {
                float vv = Vs[kk][tx*4+j];
                o0[j] += p0 * vv;
                o1[j] += p1 * vv;
            }
        }
    }
    float inv0 = 1.f / l0, inv1 = 1.f / l1;
    size_t off0 = (size_t)(b*Ln + q0 + ty*2    ) * HIDn + h*HDn + tx*4;
    size_t off1 = (size_t)(b*Ln + q0 + ty*2 + 1) * HIDn + h*HDn + tx*4;
    *(__half2*)(out + off0)     = __floats2half2_rn(o0[0]*inv0, o0[1]*inv0);
    *(__half2*)(out + off0 + 2) = __floats2half2_rn(o0[2]*inv0, o0[3]*inv0);
    *(__half2*)(out + off1)     = __floats2half2_rn(o1[0]*inv1, o1[1]*inv1);
    *(__half2*)(out + off1 + 2) = __floats2half2_rn(o1[2]*inv1, o1[3]*inv1);
}

// ---------------- causal conv1d (+mup, +bias, +silu) over xBC ----------------
__global__ __launch_bounds__(256) void conv_k(const float* __restrict__ conv_w,
                                              const float* __restrict__ conv_b) {
    int idx = blockIdx.x * blockDim.x + threadIdx.x;
    if (idx >= Bn*Ln*CONV_DIMn) return;
    int c = idx % CONV_DIMn;
    int t = (idx / CONV_DIMn) % Ln;
    int b = idx / (CONV_DIMn * Ln);
    float mup = (c < DSSMn) ? 0.9f : ((c < DSSMn + MSn) ? 0.8f : 1.1f);
    float4 w = *(const float4*)(conv_w + c*4);
    float wk[4] = {w.x, w.y, w.z, w.w};
    float s = 0.f;
#pragma unroll
    for (int k = 0; k < MKn; k++) {
        int tt = t - (MKn-1) + k;
        if (tt >= 0)
            s += g_proj[(size_t)(b*Ln + tt) * PROJ_N + DSSMn + c] * wk[k];
    }
    float acc = conv_b[c] + mup * s;
    g_conv[idx] = acc / (1.f + __expf(-acc));
}

// ---------------- dt = softplus(proj_dt * 1.2 + dt_bias) ----------------
__global__ __launch_bounds__(256) void dt_k(const float* __restrict__ dt_bias) {
    int idx = blockIdx.x * blockDim.x + threadIdx.x;
    if (idx >= TOK*MHn) return;
    int h = idx % MHn;
    float v = g_proj[(size_t)(idx / MHn) * PROJ_N + (2*DSSMn + 2*MSn) + h] * 1.2f + dt_bias[h];
    g_dt[idx] = (v > 20.f) ? v : log1pf(__expf(v));
}

// ---------------- selective scan (Mamba2), one block per (b,h), prefetched ----------------
__global__ __launch_bounds__(512) void scan_k(const float* __restrict__ A_log,
                                              const float* __restrict__ Dv) {
    int b = blockIdx.x >> 5;
    int h = blockIdx.x & 31;
    int tid = threadIdx.x;
    int p = tid >> 3;
    int s0 = (tid & 7) << 3;
    float Ah = -expf(A_log[h]);
    float Dh = Dv[h];
    float st[8] = {0,0,0,0,0,0,0,0};

    size_t base = (size_t)(b*Ln) * CONV_DIMn;
    float dt_c = g_dt[(b*Ln) * MHn + h];
    float xv_c = g_conv[base + h*MPn + p];
    float4 bv0_c = *(const float4*)(g_conv + base + DSSMn + s0);
    float4 bv1_c = *(const float4*)(g_conv + base + DSSMn + s0 + 4);
    float4 cv0_c = *(const float4*)(g_conv + base + DSSMn + MSn + s0);
    float4 cv1_c = *(const float4*)(g_conv + base + DSSMn + MSn + s0 + 4);

    for (int t = 0; t < Ln; t++) {
        float dt_n = 0.f, xv_n = 0.f;
        float4 bv0_n, bv1_n, cv0_n, cv1_n;
        if (t + 1 < Ln) {
            size_t nb = (size_t)(b*Ln + t + 1) * CONV_DIMn;
            dt_n = g_dt[(b*Ln + t + 1) * MHn + h];
            xv_n = g_conv[nb + h*MPn + p];
            bv0_n = *(const float4*)(g_conv + nb + DSSMn + s0);
            bv1_n = *(const float4*)(g_conv + nb + DSSMn + s0 + 4);
            cv0_n = *(const float4*)(g_conv + nb + DSSMn + MSn + s0);
            cv1_n = *(const float4*)(g_conv + nb + DSSMn + MSn + s0 + 4);
        } else {
            bv0_n = bv1_n = cv0_n = cv1_n = make_float4(0.f,0.f,0.f,0.f);
        }

        float dA = __expf(dt_c * Ah);
        float coef = dt_c * xv_c;
        float y = 0.f;
        st[0] = st[0]*dA + coef*bv0_c.x; y += st[0]*cv0_c.x;
        st[1] = st[1]*dA + coef*bv0_c.y; y += st[1]*cv0_c.y;
        st[2] = st[2]*dA + coef*bv0_c.z; y += st[2]*cv0_c.z;
        st[3] = st[3]*dA + coef*bv0_c.w; y += st[3]*cv0_c.w;
        st[4] = st[4]*dA + coef*bv1_c.x; y += st[4]*cv1_c.x;
        st[5] = st[5]*dA + coef*bv1_c.y; y += st[5]*cv1_c.y;
        st[6] = st[6]*dA + coef*bv1_c.z; y += st[6]*cv1_c.z;
        st[7] = st[7]*dA + coef*bv1_c.w; y += st[7]*cv1_c.w;
        y += __shfl_xor_sync(0xffffffffu, y, 1);
        y += __shfl_xor_sync(0xffffffffu, y, 2);
        y += __shfl_xor_sync(0xffffffffu, y, 4);
        if ((tid & 7) == 0)
            g_y[(size_t)(b*Ln + t) * DSSMn + h*MPn + p] = y + xv_c * Dh;

        dt_c = dt_n; xv_c = xv_n;
        bv0_c = bv0_n; bv1_c = bv1_n; cv0_c = cv0_n; cv1_c = cv1_n;
    }
}

// ---------------- gate (y * silu(z)) + RMSNorm; fp16 output ----------------
__global__ __launch_bounds__(256) void gate_rms_k(const float* __restrict__ nw) {
    int row = blockIdx.x;
    const float* zp = g_proj + (size_t)row * PROJ_N;
    float* yp = g_y + (size_t)row * DSSMn;
    __half* op = g_yh + (size_t)row * DSSMn;
    float ss = 0.f;
    for (int i = threadIdx.x; i < DSSMn; i += 256) {
        float z = zp[i];
        float gval = yp[i] * (z / (1.f + __expf(-z)));
        yp[i] = gval;
        ss += gval * gval;
    }
    ss = block_sum256(ss);
    float sc = rsqrtf(ss * (1.f/DSSMn) + EPSf);
    for (int i = threadIdx.x; i < DSSMn; i += 256)
        op[i] = __float2half_rn(yp[i] * sc * nw[i]);
}

// ---------------- fused: h = attn+ssm+resid (fp32 g_h) ; h2 = rms(h)*w (fp16 g_h2h) ----------------
__global__ __launch_bounds__(256) void combine_rms_k(const float* __restrict__ hidden,
                                                     const float* __restrict__ w) {
    __shared__ float hrow[HIDn];
    int row = blockIdx.x;
    const float4* ap = (const float4*)(g_attn_h + (size_t)row * HIDn);
    const float4* sp = (const float4*)(g_ssm_h + (size_t)row * HIDn);
    const float4* rp = (const float4*)(hidden + (size_t)row * HIDn);
    float4* hp = (float4*)(g_h + (size_t)row * HIDn);
    float ss = 0.f;
    for (int i = threadIdx.x; i < HIDn/4; i += 256) {
        float4 a = ap[i], s = sp[i], r = rp[i];
        float4 o;
        o.x = a.x + s.x + r.x; o.y = a.y + s.y + r.y;
        o.z = a.z + s.z + r.z; o.w = a.w + s.w + r.w;
        hp[i] = o;
        ((float4*)hrow)[i] = o;
        ss += o.x*o.x + o.y*o.y + o.z*o.z + o.w*o.w;
    }
    ss = block_sum256(ss);
    float sc = rsqrtf(ss * (1.0f/HIDn) + EPSf);
    __half2* o2 = (__half2*)(g_h2h + (size_t)row * HIDn);
    const float4* wr = (const float4*)w;
    for (int i = threadIdx.x; i < HIDn/4; i += 256) {
        float4 v = ((float4*)hrow)[i]; float4 ww = wr[i];
        o2[i*2]   = __floats2half2_rn(v.x*sc*ww.x, v.y*sc*ww.y);
        o2[i*2+1] = __floats2half2_rn(v.z*sc*ww.z, v.w*sc*ww.w);
    }
}

// ---------------- host launcher ----------------
static void* symv(const void* s) {
    void* p = nullptr;
    cudaGetSymbolAddress(&p, s);
    return p;
}

extern "C" void kernel_launch(void* const* d_in, const int* in_sizes, int n_in,
                              void* d_out, int out_size) {
    const float* hidden     = (const float*)d_in[0];
    const int*   positions  = (const int*)  d_in[1];
    const float* w_in_ln    = (const float*)d_in[2];
    const float* qkv_w      = (const float*)d_in[3];
    const float* o_w        = (const float*)d_in[4];
    const float* in_proj_w  = (const float*)d_in[5];
    const float* conv_w     = (const float*)d_in[6];
    const float* conv_b     = (const float*)d_in[7];
    const float* A_log      = (const float*)d_in[8];
    const float* dt_bias    = (const float*)d_in[9];
    const float* Dv         = (const float*)d_in[10];
    const float* ssm_norm_w = (const float*)d_in[11];
    const float* out_proj_w = (const float*)d_in[12];
    const float* w_pre_ff   = (const float*)d_in[13];
    const float* gate_up_w  = (const float*)d_in[14];
    const float* down_w     = (const float*)d_in[15];
    float* out = (float*)d_out;

    __half* p_hs    = (__half*)symv(g_hs);
    float*  p_qkv   = (float*) symv(g_qkv);
    __half* p_attn  = (__half*)symv(g_attn);
    float*  p_attn_h= (float*) symv(g_attn_h);
    float*  p_y     = (float*) symv(g_y);
    __half* p_yh    = (__half*)symv(g_yh);
    float*  p_ssm_h = (float*) symv(g_ssm_h);
    float*  p_h     = (float*) symv(g_h);
    __half* p_h2h   = (__half*)symv(g_h2h);
    __half* p_act   = (__half*)symv(g_act);
    float*  p_proj  = (float*) symv(g_proj);
    __half* p_wqkv  = (__half*)symv(g_wqkv);
    __half* p_wo    = (__half*)symv(g_wo);
    __half* p_win   = (__half*)symv(g_win);
    __half* p_wout  = (__half*)symv(g_wout);
    __half* p_wgu   = (__half*)symv(g_wgu);
    __half* p_wdn   = (__half*)symv(g_wdn);

    // 0. fp16-convert the weights (gate_up also row-interleaved + GATE_MULT folded)
    {
        struct { const float* in; __half* out; size_t n; } W[5] = {
            {qkv_w,     p_wqkv, (size_t)QKV_N*HIDn},
            {o_w,       p_wo,   (size_t)HIDn*HIDn},
            {in_proj_w, p_win,  (size_t)PROJ_N*HIDn},
            {out_proj_w,p_wout, (size_t)HIDn*DSSMn},
            {down_w,    p_wdn,  (size_t)HIDn*INTERn},
        };
        for (int i = 0; i < 5; i++) {
            int n4 = (int)(W[i].n / 4);
            cvtw_k<<<(n4 + 255)/256, 256>>>(W[i].in, W[i].out, n4);
        }
        int n4gu = 2*INTERn*(HIDn/4);
        cvtw_gu_k<<<(n4gu + 255)/256, 256>>>(gate_up_w, p_wgu);
    }

    // 1. input RMSNorm (fp16 output)
    rmsnorm_k<<<TOK, 256>>>(hidden, w_in_ln, p_hs);

    // 2. qkv projection (fold ATTN_IN)
    tgemm_nt<<<dim3(QKV_N/128, TOK/128), 256>>>(p_hs, p_wqkv, p_qkv, nullptr,
                                                TOK, QKV_N, HIDn, ATTN_IN);
    // 3. RoPE + key mult
    {
        int total = TOK * (NHn + NKVn) * (HDn/2);
        rope_k<<<(total + 255)/256, 256>>>(positions);
    }
    // 4. attention (scalar flash)
    attn_k<<<dim3(Ln/32, Bn*NHn), 256>>>(p_qkv, p_attn);
    // 5. o projection (fold ATTN_OUT)
    tgemm_nt<<<dim3(HIDn/128, TOK/128), 256>>>(p_attn, p_wo, p_attn_h, nullptr,
                                               TOK, HIDn, HIDn, ATTN_OUT);

    // 6. SSM in_proj (fold SSM_IN)
    tgemm_nt<<<dim3((PROJ_N + 127)/128, TOK/128), 256>>>(p_hs, p_win, p_proj, nullptr,
                                                         TOK, PROJ_N, HIDn, SSM_IN);
    // 7. conv + silu ; dt softplus
    conv_k<<<(Bn*Ln*CONV_DIMn + 255)/256, 256>>>(conv_w, conv_b);
    dt_k<<<(TOK*MHn + 255)/256, 256>>>(dt_bias);
    // 8. selective scan (prefetched)
    scan_k<<<Bn*MHn, 512>>>(A_log, Dv);
    // 9. gate + RMS (fp16 output)
    gate_rms_k<<<TOK, 256>>>(ssm_norm_w);
    // 10. out_proj (fold SSM_OUT)
    tgemm_nt<<<dim3(HIDn/128, TOK/128), 256>>>(p_yh, p_wout, p_ssm_h, nullptr,
                                               TOK, HIDn, DSSMn, SSM_OUT);

    // 11. residual combine + pre-FF RMSNorm (fused)
    combine_rms_k<<<TOK, 256>>>(hidden, w_pre_ff);

    // 12. MLP: gate_up with fused SwiGLU epilogue -> g_act (fp16), then down (+resid)
    tgemm_gu<<<dim3((2*INTERn)/128, TOK/128), 256>>>(p_h2h, p_wgu, p_act,
                                                     TOK, 2*INTERn, HIDn);
    tgemm_nt<<<dim3(HIDn/128, TOK/128), 256>>>(p_act, p_wdn, out, p_h,
                                               TOK, HIDn, INTERn, DOWN_MULT);
}